// round 8
// baseline (speedup 1.0000x reference)
#include <cuda_runtime.h>
#include <cuda_bf16.h>
#include <math.h>
#include <stdint.h>

#define NN 50000
#define EE 800000
#define EP (EE + NN)   // 850000 edges incl. self loops
#define HEADS 8
#define HID 64
#define INF_ 256
#define OUTF 40
#define LRELU 0.2f

// ---------------- scratch ------------------------------------------------------
__device__ float g_Wc[512 * 512];
__device__ float g_xr[(size_t)NN * INF_];    // rna-rounded x
__device__ float g_Wh[(size_t)NN * 512];
__device__ float g_h1[(size_t)NN * 512];
__device__ float g_h2[(size_t)NN * 512];
__device__ float g_ssrc[NN * HEADS];
__device__ float g_sdst[NN * HEADS];
__device__ float g_val[(size_t)EP * HEADS];   // [h*EP + p]
__device__ float g_inv[NN * HEADS];
__device__ int   g_counts[NN];
__device__ int   g_offsets[NN + 1];
__device__ int   g_cursor[NN];
__device__ int   g_csr_src[EP];

// ---------------- tf32 helper ----------------------------------------------------
__device__ __forceinline__ float rna_tf32(float x) {
    unsigned r;
    asm("cvt.rna.tf32.f32 %0, %1;" : "=r"(r) : "f"(x));
    return __uint_as_float(r);
}

// ---------------- CSR build ----------------------------------------------------
__global__ void zero_kernel() {
    int i = blockIdx.x * blockDim.x + threadIdx.x;
    for (; i < NN; i += gridDim.x * blockDim.x) { g_counts[i] = 0; g_cursor[i] = 0; }
}

__global__ void hist_kernel(const int* __restrict__ ei) {
    int e = blockIdx.x * blockDim.x + threadIdx.x;
    if (e >= EP) return;
    int dst = (e < EE) ? ei[EE + e] : (e - EE);
    atomicAdd(&g_counts[dst], 1);
}

__global__ void scan_kernel() {
    __shared__ int s[1024];
    int tid = threadIdx.x;
    int carry = 0;
    for (int base = 0; base < NN; base += 1024) {
        int i = base + tid;
        int v = (i < NN) ? g_counts[i] : 0;
        s[tid] = v;
        __syncthreads();
        for (int off = 1; off < 1024; off <<= 1) {
            int t = (tid >= off) ? s[tid - off] : 0;
            __syncthreads();
            s[tid] += t;
            __syncthreads();
        }
        if (i < NN) g_offsets[i] = carry + s[tid] - v;
        carry += s[1023];
        __syncthreads();
    }
    if (tid == 0) g_offsets[NN] = carry;
}

__global__ void fill_kernel(const int* __restrict__ ei) {
    int e = blockIdx.x * blockDim.x + threadIdx.x;
    if (e >= EP) return;
    int src = (e < EE) ? ei[e] : (e - EE);
    int dst = (e < EE) ? ei[EE + e] : (e - EE);
    int pos = g_offsets[dst] + atomicAdd(&g_cursor[dst], 1);
    g_csr_src[pos] = src;
}

// ---------------- round x to tf32 (float4) --------------------------------------
__global__ void round_kernel(const float* __restrict__ in, float* __restrict__ out, int n4) {
    int i = blockIdx.x * blockDim.x + threadIdx.x;
    if (i >= n4) return;
    float4 v = __ldg((const float4*)in + i);
    v.x = rna_tf32(v.x); v.y = rna_tf32(v.y);
    v.z = rna_tf32(v.z); v.w = rna_tf32(v.w);
    ((float4*)out)[i] = v;
}

// ---------------- weight pack: [H,K,F] -> [K, H*F], rna-rounded -----------------
__global__ void pack_kernel(const float* __restrict__ W, float* __restrict__ out,
                            int K, int H, int F) {
    int idx = blockIdx.x * blockDim.x + threadIdx.x;
    int tot = K * H * F;
    if (idx >= tot) return;
    int k = idx / (H * F);
    int c = idx % (H * F);
    int h = c / F, j = c % F;
    out[idx] = rna_tf32(W[(size_t)h * K * F + (size_t)k * F + j]);
}

// ---------------- pack Wout [512,40] -> [512,64] zero-padded, rounded -----------
__global__ void pack_out_kernel(const float* __restrict__ W, float* __restrict__ out) {
    int idx = blockIdx.x * blockDim.x + threadIdx.x;
    if (idx >= 512 * 64) return;
    int k = idx >> 6, c = idx & 63;
    out[idx] = (c < OUTF) ? rna_tf32(W[k * OUTF + c]) : 0.f;
}

// ---------------- cp.async helpers ---------------------------------------------
__device__ __forceinline__ void cp16(uint32_t dst, const void* src, bool pred) {
    int sz = pred ? 16 : 0;
    asm volatile("cp.async.ca.shared.global [%0], [%1], 16, %2;\n"
                 :: "r"(dst), "l"(src), "r"(sz));
}
#define CP_COMMIT() asm volatile("cp.async.commit_group;\n" ::: "memory")
#define CP_WAIT0()  asm volatile("cp.async.wait_group 0;\n" ::: "memory")
#define CP_WAIT1()  asm volatile("cp.async.wait_group 1;\n" ::: "memory")

// ---------------- TF32 GEMM, cp.async 3-stage pipeline --------------------------
// BM=128 BN=128 BK=16, 256 threads = 8 warps (4m x 2n), warp tile 32x64.
#define APAD 20
#define BPAD 136
#define ASZ (128 * APAD)
#define BSZ (16 * BPAD)
#define STAGE_WORDS (ASZ + BSZ)
#define GEMM_SMEM_BYTES (STAGE_WORDS * 3 * 4)
__global__ __launch_bounds__(256) void gemm_tf32_kernel(const float* __restrict__ A,
                                                        const float* __restrict__ B,
                                                        float* __restrict__ C,
                                                        int M, int Nc, int K) {
    extern __shared__ unsigned smem_dyn[];
    int tid = threadIdx.x;
    int wid = tid >> 5, lane = tid & 31;
    int ly = lane >> 2, lx = lane & 3;
    int wm = wid >> 1, wn = wid & 1;
    int bm = blockIdx.y * 128, bn = blockIdx.x * 128;

    unsigned* AsP[3];
    unsigned* BsP[3];
    uint32_t sA[3], sB[3];
#pragma unroll
    for (int s = 0; s < 3; s++) {
        AsP[s] = smem_dyn + s * STAGE_WORDS;
        BsP[s] = AsP[s] + ASZ;
        sA[s] = (uint32_t)__cvta_generic_to_shared(AsP[s]);
        sB[s] = (uint32_t)__cvta_generic_to_shared(BsP[s]);
    }

    float c[2][8][4];
#pragma unroll
    for (int i = 0; i < 2; i++)
#pragma unroll
        for (int j = 0; j < 8; j++)
#pragma unroll
            for (int q = 0; q < 4; q++) c[i][j][q] = 0.f;

    int arow0 = tid >> 2, aq0 = tid & 3;
    int arow1 = (tid + 256) >> 2, aq1 = (tid + 256) & 3;
    int brow0 = tid >> 5, bq0 = tid & 31;
    int brow1 = (tid + 256) >> 5, bq1 = (tid + 256) & 31;
    bool bp0 = (bn + bq0 * 4 + 3) < Nc;
    bool bp1 = (bn + bq1 * 4 + 3) < Nc;

#define ISSUE(buf, k0) do { \
        cp16(sA[buf] + (arow0 * APAD + aq0 * 4) * 4, \
             A + (size_t)(bm + arow0) * K + (k0) + aq0 * 4, (bm + arow0) < M); \
        cp16(sA[buf] + (arow1 * APAD + aq1 * 4) * 4, \
             A + (size_t)(bm + arow1) * K + (k0) + aq1 * 4, (bm + arow1) < M); \
        cp16(sB[buf] + (brow0 * BPAD + bq0 * 4) * 4, \
             B + (size_t)((k0) + brow0) * Nc + bn + bq0 * 4, bp0); \
        cp16(sB[buf] + (brow1 * BPAD + bq1 * 4) * 4, \
             B + (size_t)((k0) + brow1) * Nc + bn + bq1 * 4, bp1); \
        CP_COMMIT(); \
    } while (0)

    int ntiles = K / 16;
    ISSUE(0, 0);
    ISSUE(1, 16);

    int cur = 0;
    for (int t = 0; t < ntiles; t++) {
        if (t + 1 < ntiles) { CP_WAIT1(); } else { CP_WAIT0(); }
        __syncthreads();
        if (t + 2 < ntiles) {
            int nb = cur + 2; if (nb >= 3) nb -= 3;
            ISSUE(nb, (t + 2) * 16);
        }

        const unsigned* Asc = AsP[cur];
        const unsigned* Bsc = BsP[cur];
#pragma unroll
        for (int kk = 0; kk < 16; kk += 8) {
            unsigned af[2][4];
#pragma unroll
            for (int mt = 0; mt < 2; mt++) {
                int mrow = wm * 32 + mt * 16 + ly;
                af[mt][0] = Asc[(mrow) * APAD + kk + lx];
                af[mt][1] = Asc[(mrow + 8) * APAD + kk + lx];
                af[mt][2] = Asc[(mrow) * APAD + kk + lx + 4];
                af[mt][3] = Asc[(mrow + 8) * APAD + kk + lx + 4];
            }
            unsigned bf[8][2];
#pragma unroll
            for (int nt = 0; nt < 8; nt++) {
                int ncol = wn * 64 + nt * 8 + ly;
                bf[nt][0] = Bsc[(kk + lx) * BPAD + ncol];
                bf[nt][1] = Bsc[(kk + lx + 4) * BPAD + ncol];
            }
#pragma unroll
            for (int mt = 0; mt < 2; mt++)
#pragma unroll
                for (int nt = 0; nt < 8; nt++) {
                    asm volatile(
                        "mma.sync.aligned.m16n8k8.row.col.f32.tf32.tf32.f32 "
                        "{%0,%1,%2,%3}, {%4,%5,%6,%7}, {%8,%9}, {%0,%1,%2,%3};\n"
                        : "+f"(c[mt][nt][0]), "+f"(c[mt][nt][1]),
                          "+f"(c[mt][nt][2]), "+f"(c[mt][nt][3])
                        : "r"(af[mt][0]), "r"(af[mt][1]), "r"(af[mt][2]), "r"(af[mt][3]),
                          "r"(bf[nt][0]), "r"(bf[nt][1]));
                }
        }
        __syncthreads();
        if (++cur == 3) cur = 0;
    }
#undef ISSUE

#pragma unroll
    for (int mt = 0; mt < 2; mt++) {
#pragma unroll
        for (int nt = 0; nt < 8; nt++) {
            int r0 = bm + wm * 32 + mt * 16 + ly;
            int col = bn + wn * 64 + nt * 8 + 2 * lx;
            if (col < Nc) {
                if (r0 < M)
                    *(float2*)(C + (size_t)r0 * Nc + col) = make_float2(c[mt][nt][0], c[mt][nt][1]);
                int r1 = r0 + 8;
                if (r1 < M)
                    *(float2*)(C + (size_t)r1 * Nc + col) = make_float2(c[mt][nt][2], c[mt][nt][3]);
            }
        }
    }
}

// ---------------- scores (8 heads, F=64): warp per node ------------------------
__global__ void scores8_kernel(const float* __restrict__ Wh, const float* __restrict__ a,
                               float* __restrict__ ssrc, float* __restrict__ sdst) {
    int n = (blockIdx.x * blockDim.x + threadIdx.x) >> 5;
    int lane = threadIdx.x & 31;
    if (n >= NN) return;
    int h = lane >> 2, q = lane & 3;
    const float* w = Wh + (size_t)n * 512 + h * 64;
    const float* av = a + h * 128;
    float ss = 0.f, sd = 0.f;
#pragma unroll
    for (int it = 0; it < 4; it++) {
        int f = q * 4 + it * 16;
        float4 x  = *(const float4*)(w + f);
        float4 as = __ldg((const float4*)(av + f));
        float4 ad = __ldg((const float4*)(av + 64 + f));
        ss += x.x * as.x + x.y * as.y + x.z * as.z + x.w * as.w;
        sd += x.x * ad.x + x.y * ad.y + x.z * ad.z + x.w * ad.w;
    }
    ss += __shfl_xor_sync(0xffffffffu, ss, 1);
    ss += __shfl_xor_sync(0xffffffffu, ss, 2);
    sd += __shfl_xor_sync(0xffffffffu, sd, 1);
    sd += __shfl_xor_sync(0xffffffffu, sd, 2);
    if (q == 0) { ssrc[n * 8 + h] = ss; sdst[n * 8 + h] = sd; }
}

// ---------------- scores layer 2 (H=1, F=40, Wh row stride 64) -----------------
__global__ void scores_l2_kernel(const float* __restrict__ Wh, const float* __restrict__ a,
                                 float* __restrict__ ssrc, float* __restrict__ sdst) {
    int n = blockIdx.x * blockDim.x + threadIdx.x;
    if (n >= NN) return;
    const float* w = Wh + (size_t)n * 64;
    float ss = 0.f, sd = 0.f;
#pragma unroll
    for (int j = 0; j < OUTF; j++) {
        float x = w[j];
        ss += x * __ldg(a + j);
        sd += x * __ldg(a + OUTF + j);
    }
    ssrc[n] = ss;
    sdst[n] = sd;
}

// ---------------- segment softmax, 8 heads at once ------------------------------
__global__ void alpha8_kernel(const float* __restrict__ ssrc, const float* __restrict__ sdst,
                              float* __restrict__ val, float* __restrict__ inv) {
    int w = (blockIdx.x * blockDim.x + threadIdx.x) >> 5;
    int lane = threadIdx.x & 31;
    if (w >= NN) return;
    int beg = g_offsets[w], end = g_offsets[w + 1];
    float4 d0 = __ldg((const float4*)(sdst + w * 8));
    float4 d1 = __ldg((const float4*)(sdst + w * 8 + 4));
    float sdh[8] = {d0.x, d0.y, d0.z, d0.w, d1.x, d1.y, d1.z, d1.w};
    float m[8];
#pragma unroll
    for (int h = 0; h < 8; h++) m[h] = -1e30f;

    for (int p = beg + lane; p < end; p += 32) {
        int src = g_csr_src[p];
        float4 s0 = __ldg((const float4*)(ssrc + src * 8));
        float4 s1 = __ldg((const float4*)(ssrc + src * 8 + 4));
        float sv[8] = {s0.x, s0.y, s0.z, s0.w, s1.x, s1.y, s1.z, s1.w};
#pragma unroll
        for (int h = 0; h < 8; h++) {
            float v = sv[h] + sdh[h];
            v = v > 0.f ? v : LRELU * v;
            val[(size_t)h * EP + p] = v;
            m[h] = fmaxf(m[h], v);
        }
    }
#pragma unroll
    for (int h = 0; h < 8; h++)
#pragma unroll
        for (int o = 16; o; o >>= 1) m[h] = fmaxf(m[h], __shfl_xor_sync(0xffffffffu, m[h], o));

    float s[8];
#pragma unroll
    for (int h = 0; h < 8; h++) s[h] = 0.f;
    for (int p = beg + lane; p < end; p += 32) {
#pragma unroll
        for (int h = 0; h < 8; h++) {
            float ex = __expf(val[(size_t)h * EP + p] - m[h]);
            val[(size_t)h * EP + p] = ex;
            s[h] += ex;
        }
    }
#pragma unroll
    for (int h = 0; h < 8; h++)
#pragma unroll
        for (int o = 16; o; o >>= 1) s[h] += __shfl_xor_sync(0xffffffffu, s[h], o);
    if (lane == 0) {
#pragma unroll
        for (int h = 0; h < 8; h++) inv[w * 8 + h] = 1.0f / s[h];
    }
}

// ---------------- segment softmax, 1 head (layer 2) ----------------------------
__global__ void alpha1_kernel(const float* __restrict__ ssrc, const float* __restrict__ sdst,
                              float* __restrict__ val, float* __restrict__ inv) {
    int w = (blockIdx.x * blockDim.x + threadIdx.x) >> 5;
    int lane = threadIdx.x & 31;
    if (w >= NN) return;
    int beg = g_offsets[w], end = g_offsets[w + 1];
    float sdh = __ldg(sdst + w);
    float m = -1e30f;
    for (int p = beg + lane; p < end; p += 32) {
        float v = __ldg(ssrc + g_csr_src[p]) + sdh;
        v = v > 0.f ? v : LRELU * v;
        val[p] = v;
        m = fmaxf(m, v);
    }
#pragma unroll
    for (int o = 16; o; o >>= 1) m = fmaxf(m, __shfl_xor_sync(0xffffffffu, m, o));
    float s = 0.f;
    for (int p = beg + lane; p < end; p += 32) {
        float ex = __expf(val[p] - m);
        val[p] = ex;
        s += ex;
    }
#pragma unroll
    for (int o = 16; o; o >>= 1) s += __shfl_xor_sync(0xffffffffu, s, o);
    if (lane == 0) inv[w] = 1.0f / s;
}

// ---------------- aggregation, Ftot=512 (unroll-4, epilogue elu+round) ---------
__global__ __launch_bounds__(128) void aggregate512_kernel(const float* __restrict__ Wh,
                                                           const float* __restrict__ val,
                                                           const float* __restrict__ inv,
                                                           float* __restrict__ out) {
    int d = blockIdx.x;
    int t = threadIdx.x;
    int h = t >> 4;
    int beg = g_offsets[d], end = g_offsets[d + 1];
    const float4* W4 = (const float4*)Wh;
    const float* vh = val + (size_t)h * EP;
    float4 acc = make_float4(0.f, 0.f, 0.f, 0.f);
    int p = beg;
    for (; p + 3 < end; p += 4) {
        int s0 = g_csr_src[p],     s1 = g_csr_src[p + 1];
        int s2 = g_csr_src[p + 2], s3 = g_csr_src[p + 3];
        float e0 = __ldg(&vh[p]),     e1 = __ldg(&vh[p + 1]);
        float e2 = __ldg(&vh[p + 2]), e3 = __ldg(&vh[p + 3]);
        float4 w0 = __ldg(&W4[(size_t)s0 * 128 + t]);
        float4 w1 = __ldg(&W4[(size_t)s1 * 128 + t]);
        float4 w2 = __ldg(&W4[(size_t)s2 * 128 + t]);
        float4 w3 = __ldg(&W4[(size_t)s3 * 128 + t]);
        acc.x += e0 * w0.x + e1 * w1.x + e2 * w2.x + e3 * w3.x;
        acc.y += e0 * w0.y + e1 * w1.y + e2 * w2.y + e3 * w3.y;
        acc.z += e0 * w0.z + e1 * w1.z + e2 * w2.z + e3 * w3.z;
        acc.w += e0 * w0.w + e1 * w1.w + e2 * w2.w + e3 * w3.w;
    }
    for (; p < end; p++) {
        int s0 = g_csr_src[p];
        float e0 = __ldg(&vh[p]);
        float4 w0 = __ldg(&W4[(size_t)s0 * 128 + t]);
        acc.x += e0 * w0.x; acc.y += e0 * w0.y;
        acc.z += e0 * w0.z; acc.w += e0 * w0.w;
    }
    float iv = __ldg(&inv[d * 8 + h]);
    acc.x *= iv; acc.y *= iv; acc.z *= iv; acc.w *= iv;
    acc.x = rna_tf32(acc.x > 0.f ? acc.x : expm1f(acc.x));
    acc.y = rna_tf32(acc.y > 0.f ? acc.y : expm1f(acc.y));
    acc.z = rna_tf32(acc.z > 0.f ? acc.z : expm1f(acc.z));
    acc.w = rna_tf32(acc.w > 0.f ? acc.w : expm1f(acc.w));
    ((float4*)out)[(size_t)d * 128 + t] = acc;
}

// ---------------- aggregation layer 2 -------------------------------------------
__global__ __launch_bounds__(64) void aggregate_l2_kernel(const float* __restrict__ Wh,
                                                          const float* __restrict__ val,
                                                          const float* __restrict__ inv,
                                                          float* __restrict__ out) {
    int d = blockIdx.x;
    int f = threadIdx.x;
    int beg = g_offsets[d], end = g_offsets[d + 1];
    float acc = 0.f;
    for (int p = beg; p < end; p++) {
        int src = g_csr_src[p];
        float ex = __ldg(&val[p]);
        if (f < OUTF) acc += ex * Wh[(size_t)src * 64 + f];
    }
    if (f < OUTF) out[(size_t)d * OUTF + f] = acc * __ldg(&inv[d]);
}

// ---------------- final elu + log_softmax ---------------------------------------
__global__ void final_kernel(const float* __restrict__ raw, float* __restrict__ out) {
    int w = (blockIdx.x * blockDim.x + threadIdx.x) >> 5;
    int lane = threadIdx.x & 31;
    if (w >= NN) return;
    int j0 = lane, j1 = lane + 32;
    float v0 = -1e30f, v1 = -1e30f;
    if (j0 < OUTF) {
        float x = raw[(size_t)w * OUTF + j0];
        v0 = x > 0.f ? x : expm1f(x);
    }
    if (j1 < OUTF) {
        float x = raw[(size_t)w * OUTF + j1];
        v1 = x > 0.f ? x : expm1f(x);
    }
    float m = fmaxf(v0, v1);
#pragma unroll
    for (int o = 16; o; o >>= 1) m = fmaxf(m, __shfl_xor_sync(0xffffffffu, m, o));
    float s = 0.f;
    if (j0 < OUTF) s += __expf(v0 - m);
    if (j1 < OUTF) s += __expf(v1 - m);
#pragma unroll
    for (int o = 16; o; o >>= 1) s += __shfl_xor_sync(0xffffffffu, s, o);
    float l = logf(s) + m;
    if (j0 < OUTF) out[(size_t)w * OUTF + j0] = v0 - l;
    if (j1 < OUTF) out[(size_t)w * OUTF + j1] = v1 - l;
}

// ---------------- host orchestration ---------------------------------------------
extern "C" void kernel_launch(void* const* d_in, const int* in_sizes, int n_in,
                              void* d_out, int out_size) {
    const float* x    = (const float*)d_in[0];
    const int*   ei   = (const int*)d_in[1];
    const float* W0   = (const float*)d_in[2];
    const float* a0   = (const float*)d_in[3];
    const float* W1   = (const float*)d_in[4];
    const float* a1   = (const float*)d_in[5];
    const float* Wout = (const float*)d_in[6];
    const float* aout = (const float*)d_in[7];
    float* out = (float*)d_out;

    float *Wc, *xr, *Wh, *h1, *h2, *ssrc, *sdst, *val, *inv;
    cudaGetSymbolAddress((void**)&Wc, g_Wc);
    cudaGetSymbolAddress((void**)&xr, g_xr);
    cudaGetSymbolAddress((void**)&Wh, g_Wh);
    cudaGetSymbolAddress((void**)&h1, g_h1);
    cudaGetSymbolAddress((void**)&h2, g_h2);
    cudaGetSymbolAddress((void**)&ssrc, g_ssrc);
    cudaGetSymbolAddress((void**)&sdst, g_sdst);
    cudaGetSymbolAddress((void**)&val, g_val);
    cudaGetSymbolAddress((void**)&inv, g_inv);

    static int smem_set = 0;
    if (!smem_set) {
        cudaFuncSetAttribute(gemm_tf32_kernel,
                             cudaFuncAttributeMaxDynamicSharedMemorySize, GEMM_SMEM_BYTES);
        smem_set = 1;
    }

    const int TB = 256;
    dim3 tf32_grid(4, (NN + 127) / 128);
    dim3 tf32_grid_out(1, (NN + 127) / 128);

    // Launch #4 (ncu capture point) = layer-0 tf32 GEMM.
    pack_kernel<<<(256 * 512 + TB - 1) / TB, TB>>>(W0, Wc, INF_, HEADS, HID);     // 1
    round_kernel<<<(NN * INF_ / 4 + TB - 1) / TB, TB>>>(x, xr, NN * INF_ / 4);     // 2
    zero_kernel<<<(NN + TB - 1) / TB, TB>>>();                                     // 3
    gemm_tf32_kernel<<<tf32_grid, 256, GEMM_SMEM_BYTES>>>(xr, Wc, Wh, NN, 512, INF_); // 4
    hist_kernel<<<(EP + TB - 1) / TB, TB>>>(ei);                                   // 5
    scan_kernel<<<1, 1024>>>();                                                    // 6
    fill_kernel<<<(EP + TB - 1) / TB, TB>>>(ei);                                   // 7
    scores8_kernel<<<(NN * 32 + TB - 1) / TB, TB>>>(Wh, a0, ssrc, sdst);
    alpha8_kernel<<<(NN + 7) / 8, 256>>>(ssrc, sdst, val, inv);
    aggregate512_kernel<<<NN, 128>>>(Wh, val, inv, h1);

    // ---- layer 1 ----
    pack_kernel<<<(512 * 512 + TB - 1) / TB, TB>>>(W1, Wc, 512, HEADS, HID);
    gemm_tf32_kernel<<<tf32_grid, 256, GEMM_SMEM_BYTES>>>(h1, Wc, Wh, NN, 512, 512);
    scores8_kernel<<<(NN * 32 + TB - 1) / TB, TB>>>(Wh, a1, ssrc, sdst);
    alpha8_kernel<<<(NN + 7) / 8, 256>>>(ssrc, sdst, val, inv);
    aggregate512_kernel<<<NN, 128>>>(Wh, val, inv, h2);

    // ---- layer 2 ----
    pack_out_kernel<<<(512 * 64 + TB - 1) / TB, TB>>>(Wout, Wc);
    gemm_tf32_kernel<<<tf32_grid_out, 256, GEMM_SMEM_BYTES>>>(h2, Wc, Wh, NN, 64, 512);
    scores_l2_kernel<<<(NN + TB - 1) / TB, TB>>>(Wh, aout, ssrc, sdst);
    alpha1_kernel<<<(NN + 7) / 8, 256>>>(ssrc, sdst, val, inv);
    aggregate_l2_kernel<<<NN, 64>>>(Wh, val, inv, h1);

    // ---- elu + log_softmax ----
    final_kernel<<<(NN + 7) / 8, 256>>>(h1, out);
}

// round 9
// speedup vs baseline: 1.1036x; 1.1036x over previous
#include <cuda_runtime.h>
#include <cuda_bf16.h>
#include <math.h>
#include <stdint.h>

#define NN 50000
#define EE 800000
#define EP (EE + NN)   // 850000 edges incl. self loops
#define HEADS 8
#define HID 64
#define INF_ 256
#define OUTF 40
#define LRELU 0.2f

// ---------------- scratch ------------------------------------------------------
__device__ float g_Wc[512 * 512];
__device__ float g_xr[(size_t)NN * INF_];    // rna-rounded x
__device__ float g_Wh[(size_t)NN * 512];
__device__ float g_h1[(size_t)NN * 512];
__device__ float g_h2[(size_t)NN * 512];
__device__ float g_ssrc[NN * HEADS];
__device__ float g_sdst[NN * HEADS];
__device__ float g_val[(size_t)EP * HEADS];   // [h*EP + p]
__device__ float g_inv[NN * HEADS];
__device__ int   g_counts[NN];
__device__ int   g_offsets[NN + 1];
__device__ int   g_cursor[NN];
__device__ int   g_csr_src[EP];

// ---------------- tf32 helper ----------------------------------------------------
__device__ __forceinline__ float rna_tf32(float x) {
    unsigned r;
    asm("cvt.rna.tf32.f32 %0, %1;" : "=r"(r) : "f"(x));
    return __uint_as_float(r);
}

// ---------------- CSR build ----------------------------------------------------
__global__ void zero_kernel() {
    int i = blockIdx.x * blockDim.x + threadIdx.x;
    for (; i < NN; i += gridDim.x * blockDim.x) { g_counts[i] = 0; g_cursor[i] = 0; }
}

__global__ void hist_kernel(const int* __restrict__ ei) {
    int e = blockIdx.x * blockDim.x + threadIdx.x;
    if (e >= EP) return;
    int dst = (e < EE) ? ei[EE + e] : (e - EE);
    atomicAdd(&g_counts[dst], 1);
}

__global__ void scan_kernel() {
    __shared__ int s[1024];
    int tid = threadIdx.x;
    int carry = 0;
    for (int base = 0; base < NN; base += 1024) {
        int i = base + tid;
        int v = (i < NN) ? g_counts[i] : 0;
        s[tid] = v;
        __syncthreads();
        for (int off = 1; off < 1024; off <<= 1) {
            int t = (tid >= off) ? s[tid - off] : 0;
            __syncthreads();
            s[tid] += t;
            __syncthreads();
        }
        if (i < NN) g_offsets[i] = carry + s[tid] - v;
        carry += s[1023];
        __syncthreads();
    }
    if (tid == 0) g_offsets[NN] = carry;
}

__global__ void fill_kernel(const int* __restrict__ ei) {
    int e = blockIdx.x * blockDim.x + threadIdx.x;
    if (e >= EP) return;
    int src = (e < EE) ? ei[e] : (e - EE);
    int dst = (e < EE) ? ei[EE + e] : (e - EE);
    int pos = g_offsets[dst] + atomicAdd(&g_cursor[dst], 1);
    g_csr_src[pos] = src;
}

// ---------------- round x to tf32 (float4) --------------------------------------
__global__ void round_kernel(const float* __restrict__ in, float* __restrict__ out, int n4) {
    int i = blockIdx.x * blockDim.x + threadIdx.x;
    if (i >= n4) return;
    float4 v = __ldg((const float4*)in + i);
    v.x = rna_tf32(v.x); v.y = rna_tf32(v.y);
    v.z = rna_tf32(v.z); v.w = rna_tf32(v.w);
    ((float4*)out)[i] = v;
}

// ---------------- weight pack: [H,K,F] -> [K, H*F], rna-rounded -----------------
__global__ void pack_kernel(const float* __restrict__ W, float* __restrict__ out,
                            int K, int H, int F) {
    int idx = blockIdx.x * blockDim.x + threadIdx.x;
    int tot = K * H * F;
    if (idx >= tot) return;
    int k = idx / (H * F);
    int c = idx % (H * F);
    int h = c / F, j = c % F;
    out[idx] = rna_tf32(W[(size_t)h * K * F + (size_t)k * F + j]);
}

// ---------------- pack Wout [512,40] -> [512,64] zero-padded, rounded -----------
__global__ void pack_out_kernel(const float* __restrict__ W, float* __restrict__ out) {
    int idx = blockIdx.x * blockDim.x + threadIdx.x;
    if (idx >= 512 * 64) return;
    int k = idx >> 6, c = idx & 63;
    out[idx] = (c < OUTF) ? rna_tf32(W[k * OUTF + c]) : 0.f;
}

// ---------------- cp.async helpers ---------------------------------------------
__device__ __forceinline__ void cp16(uint32_t dst, const void* src, bool pred) {
    int sz = pred ? 16 : 0;
    asm volatile("cp.async.ca.shared.global [%0], [%1], 16, %2;\n"
                 :: "r"(dst), "l"(src), "r"(sz));
}
#define CP_COMMIT() asm volatile("cp.async.commit_group;\n" ::: "memory")
#define CP_WAIT0()  asm volatile("cp.async.wait_group 0;\n" ::: "memory")
#define CP_WAIT1()  asm volatile("cp.async.wait_group 1;\n" ::: "memory")

// ---------------- TF32 GEMM, cp.async 3-stage, literal stage indices ------------
// BM=128 BN=128 BK=16, 256 threads = 8 warps (4m x 2n), warp tile 32x64.
#define APAD 20
#define BPAD 136
#define ASZ (128 * APAD)
#define BSZ (16 * BPAD)
#define STAGE_WORDS (ASZ + BSZ)
#define GEMM_SMEM_BYTES (STAGE_WORDS * 3 * 4)
__global__ __launch_bounds__(256) void gemm_tf32_kernel(const float* __restrict__ A,
                                                        const float* __restrict__ B,
                                                        float* __restrict__ C,
                                                        int M, int Nc, int K) {
    extern __shared__ unsigned sm[];
    int tid = threadIdx.x;
    int wid = tid >> 5, lane = tid & 31;
    int ly = lane >> 2, lx = lane & 3;
    int wm = wid >> 1, wn = wid & 1;
    int bm = blockIdx.y * 128, bn = blockIdx.x * 128;

    uint32_t sbase = (uint32_t)__cvta_generic_to_shared(sm);

    float c[2][8][4];
#pragma unroll
    for (int i = 0; i < 2; i++)
#pragma unroll
        for (int j = 0; j < 8; j++)
#pragma unroll
            for (int q = 0; q < 4; q++) c[i][j][q] = 0.f;

    int arow0 = tid >> 2, aq0 = tid & 3;
    int arow1 = (tid + 256) >> 2, aq1 = (tid + 256) & 3;
    int brow0 = tid >> 5, bq0 = tid & 31;
    int brow1 = (tid + 256) >> 5, bq1 = (tid + 256) & 31;
    bool bp0 = (bn + bq0 * 4 + 3) < Nc;
    bool bp1 = (bn + bq1 * 4 + 3) < Nc;

// S must be a compile-time literal -> all smem offsets constant-fold.
#define ISSUE(S, k0) do { \
        cp16(sbase + ((S) * STAGE_WORDS + arow0 * APAD + aq0 * 4) * 4, \
             A + (size_t)(bm + arow0) * K + (k0) + aq0 * 4, (bm + arow0) < M); \
        cp16(sbase + ((S) * STAGE_WORDS + arow1 * APAD + aq1 * 4) * 4, \
             A + (size_t)(bm + arow1) * K + (k0) + aq1 * 4, (bm + arow1) < M); \
        cp16(sbase + ((S) * STAGE_WORDS + ASZ + brow0 * BPAD + bq0 * 4) * 4, \
             B + (size_t)((k0) + brow0) * Nc + bn + bq0 * 4, bp0); \
        cp16(sbase + ((S) * STAGE_WORDS + ASZ + brow1 * BPAD + bq1 * 4) * 4, \
             B + (size_t)((k0) + brow1) * Nc + bn + bq1 * 4, bp1); \
        CP_COMMIT(); \
    } while (0)

#define BODY(S, t) do { \
        if ((t) + 2 < ntiles) { CP_WAIT1(); } else { CP_WAIT0(); } \
        __syncthreads(); \
        if ((t) + 2 < ntiles) ISSUE(((S) + 2) % 3, ((t) + 2) * 16); \
        const unsigned* Asc = sm + (S) * STAGE_WORDS; \
        const unsigned* Bsc = Asc + ASZ; \
        _Pragma("unroll") \
        for (int kk = 0; kk < 16; kk += 8) { \
            unsigned af[2][4]; \
            _Pragma("unroll") \
            for (int mt = 0; mt < 2; mt++) { \
                int mrow = wm * 32 + mt * 16 + ly; \
                af[mt][0] = Asc[(mrow) * APAD + kk + lx]; \
                af[mt][1] = Asc[(mrow + 8) * APAD + kk + lx]; \
                af[mt][2] = Asc[(mrow) * APAD + kk + lx + 4]; \
                af[mt][3] = Asc[(mrow + 8) * APAD + kk + lx + 4]; \
            } \
            unsigned bf[8][2]; \
            _Pragma("unroll") \
            for (int nt = 0; nt < 8; nt++) { \
                int ncol = wn * 64 + nt * 8 + ly; \
                bf[nt][0] = Bsc[(kk + lx) * BPAD + ncol]; \
                bf[nt][1] = Bsc[(kk + lx + 4) * BPAD + ncol]; \
            } \
            _Pragma("unroll") \
            for (int mt = 0; mt < 2; mt++) \
                _Pragma("unroll") \
                for (int nt = 0; nt < 8; nt++) { \
                    asm volatile( \
                        "mma.sync.aligned.m16n8k8.row.col.f32.tf32.tf32.f32 " \
                        "{%0,%1,%2,%3}, {%4,%5,%6,%7}, {%8,%9}, {%0,%1,%2,%3};\n" \
                        : "+f"(c[mt][nt][0]), "+f"(c[mt][nt][1]), \
                          "+f"(c[mt][nt][2]), "+f"(c[mt][nt][3]) \
                        : "r"(af[mt][0]), "r"(af[mt][1]), "r"(af[mt][2]), "r"(af[mt][3]), \
                          "r"(bf[nt][0]), "r"(bf[nt][1])); \
                } \
        } \
    } while (0)

    int ntiles = K / 16;
    ISSUE(0, 0);
    ISSUE(1, 16);

    int nfull = ntiles - (ntiles % 3);
    for (int t = 0; t < nfull; t += 3) {
        BODY(0, t);
        BODY(1, t + 1);
        BODY(2, t + 2);
    }
    if (ntiles % 3 >= 1) BODY(0, nfull);
    if (ntiles % 3 == 2) BODY(1, nfull + 1);
#undef BODY
#undef ISSUE

    __syncthreads();
#pragma unroll
    for (int mt = 0; mt < 2; mt++) {
#pragma unroll
        for (int nt = 0; nt < 8; nt++) {
            int r0 = bm + wm * 32 + mt * 16 + ly;
            int col = bn + wn * 64 + nt * 8 + 2 * lx;
            if (col < Nc) {
                if (r0 < M)
                    *(float2*)(C + (size_t)r0 * Nc + col) = make_float2(c[mt][nt][0], c[mt][nt][1]);
                int r1 = r0 + 8;
                if (r1 < M)
                    *(float2*)(C + (size_t)r1 * Nc + col) = make_float2(c[mt][nt][2], c[mt][nt][3]);
            }
        }
    }
}

// ---------------- scores (8 heads, F=64): warp per node ------------------------
__global__ void scores8_kernel(const float* __restrict__ Wh, const float* __restrict__ a,
                               float* __restrict__ ssrc, float* __restrict__ sdst) {
    int n = (blockIdx.x * blockDim.x + threadIdx.x) >> 5;
    int lane = threadIdx.x & 31;
    if (n >= NN) return;
    int h = lane >> 2, q = lane & 3;
    const float* w = Wh + (size_t)n * 512 + h * 64;
    const float* av = a + h * 128;
    float ss = 0.f, sd = 0.f;
#pragma unroll
    for (int it = 0; it < 4; it++) {
        int f = q * 4 + it * 16;
        float4 x  = *(const float4*)(w + f);
        float4 as = __ldg((const float4*)(av + f));
        float4 ad = __ldg((const float4*)(av + 64 + f));
        ss += x.x * as.x + x.y * as.y + x.z * as.z + x.w * as.w;
        sd += x.x * ad.x + x.y * ad.y + x.z * ad.z + x.w * ad.w;
    }
    ss += __shfl_xor_sync(0xffffffffu, ss, 1);
    ss += __shfl_xor_sync(0xffffffffu, ss, 2);
    sd += __shfl_xor_sync(0xffffffffu, sd, 1);
    sd += __shfl_xor_sync(0xffffffffu, sd, 2);
    if (q == 0) { ssrc[n * 8 + h] = ss; sdst[n * 8 + h] = sd; }
}

// ---------------- scores layer 2 (H=1, F=40, Wh row stride 64) -----------------
__global__ void scores_l2_kernel(const float* __restrict__ Wh, const float* __restrict__ a,
                                 float* __restrict__ ssrc, float* __restrict__ sdst) {
    int n = blockIdx.x * blockDim.x + threadIdx.x;
    if (n >= NN) return;
    const float* w = Wh + (size_t)n * 64;
    float ss = 0.f, sd = 0.f;
#pragma unroll
    for (int j = 0; j < OUTF; j++) {
        float x = w[j];
        ss += x * __ldg(a + j);
        sd += x * __ldg(a + OUTF + j);
    }
    ssrc[n] = ss;
    sdst[n] = sd;
}

// ---------------- segment softmax, 8 heads at once ------------------------------
__global__ void alpha8_kernel(const float* __restrict__ ssrc, const float* __restrict__ sdst,
                              float* __restrict__ val, float* __restrict__ inv) {
    int w = (blockIdx.x * blockDim.x + threadIdx.x) >> 5;
    int lane = threadIdx.x & 31;
    if (w >= NN) return;
    int beg = g_offsets[w], end = g_offsets[w + 1];
    float4 d0 = __ldg((const float4*)(sdst + w * 8));
    float4 d1 = __ldg((const float4*)(sdst + w * 8 + 4));
    float sdh[8] = {d0.x, d0.y, d0.z, d0.w, d1.x, d1.y, d1.z, d1.w};
    float m[8];
#pragma unroll
    for (int h = 0; h < 8; h++) m[h] = -1e30f;

    for (int p = beg + lane; p < end; p += 32) {
        int src = g_csr_src[p];
        float4 s0 = __ldg((const float4*)(ssrc + src * 8));
        float4 s1 = __ldg((const float4*)(ssrc + src * 8 + 4));
        float sv[8] = {s0.x, s0.y, s0.z, s0.w, s1.x, s1.y, s1.z, s1.w};
#pragma unroll
        for (int h = 0; h < 8; h++) {
            float v = sv[h] + sdh[h];
            v = v > 0.f ? v : LRELU * v;
            val[(size_t)h * EP + p] = v;
            m[h] = fmaxf(m[h], v);
        }
    }
#pragma unroll
    for (int h = 0; h < 8; h++)
#pragma unroll
        for (int o = 16; o; o >>= 1) m[h] = fmaxf(m[h], __shfl_xor_sync(0xffffffffu, m[h], o));

    float s[8];
#pragma unroll
    for (int h = 0; h < 8; h++) s[h] = 0.f;
    for (int p = beg + lane; p < end; p += 32) {
#pragma unroll
        for (int h = 0; h < 8; h++) {
            float ex = __expf(val[(size_t)h * EP + p] - m[h]);
            val[(size_t)h * EP + p] = ex;
            s[h] += ex;
        }
    }
#pragma unroll
    for (int h = 0; h < 8; h++)
#pragma unroll
        for (int o = 16; o; o >>= 1) s[h] += __shfl_xor_sync(0xffffffffu, s[h], o);
    if (lane == 0) {
#pragma unroll
        for (int h = 0; h < 8; h++) inv[w * 8 + h] = 1.0f / s[h];
    }
}

// ---------------- segment softmax, 1 head (layer 2) ----------------------------
__global__ void alpha1_kernel(const float* __restrict__ ssrc, const float* __restrict__ sdst,
                              float* __restrict__ val, float* __restrict__ inv) {
    int w = (blockIdx.x * blockDim.x + threadIdx.x) >> 5;
    int lane = threadIdx.x & 31;
    if (w >= NN) return;
    int beg = g_offsets[w], end = g_offsets[w + 1];
    float sdh = __ldg(sdst + w);
    float m = -1e30f;
    for (int p = beg + lane; p < end; p += 32) {
        float v = __ldg(ssrc + g_csr_src[p]) + sdh;
        v = v > 0.f ? v : LRELU * v;
        val[p] = v;
        m = fmaxf(m, v);
    }
#pragma unroll
    for (int o = 16; o; o >>= 1) m = fmaxf(m, __shfl_xor_sync(0xffffffffu, m, o));
    float s = 0.f;
    for (int p = beg + lane; p < end; p += 32) {
        float ex = __expf(val[p] - m);
        val[p] = ex;
        s += ex;
    }
#pragma unroll
    for (int o = 16; o; o >>= 1) s += __shfl_xor_sync(0xffffffffu, s, o);
    if (lane == 0) inv[w] = 1.0f / s;
}

// ---------------- aggregation, Ftot=512 (unroll-2, epilogue elu+round) ---------
__global__ __launch_bounds__(128) void aggregate512_kernel(const float* __restrict__ Wh,
                                                           const float* __restrict__ val,
                                                           const float* __restrict__ inv,
                                                           float* __restrict__ out) {
    int d = blockIdx.x;
    int t = threadIdx.x;
    int h = t >> 4;
    int beg = g_offsets[d], end = g_offsets[d + 1];
    const float4* W4 = (const float4*)Wh;
    const float* vh = val + (size_t)h * EP;
    float4 acc = make_float4(0.f, 0.f, 0.f, 0.f);
    int p = beg;
    for (; p + 1 < end; p += 2) {
        int s0 = g_csr_src[p], s1 = g_csr_src[p + 1];
        float e0 = __ldg(&vh[p]);
        float e1 = __ldg(&vh[p + 1]);
        float4 w0 = __ldg(&W4[(size_t)s0 * 128 + t]);
        float4 w1 = __ldg(&W4[(size_t)s1 * 128 + t]);
        acc.x += e0 * w0.x + e1 * w1.x;
        acc.y += e0 * w0.y + e1 * w1.y;
        acc.z += e0 * w0.z + e1 * w1.z;
        acc.w += e0 * w0.w + e1 * w1.w;
    }
    if (p < end) {
        int s0 = g_csr_src[p];
        float e0 = __ldg(&vh[p]);
        float4 w0 = __ldg(&W4[(size_t)s0 * 128 + t]);
        acc.x += e0 * w0.x; acc.y += e0 * w0.y;
        acc.z += e0 * w0.z; acc.w += e0 * w0.w;
    }
    float iv = __ldg(&inv[d * 8 + h]);
    acc.x *= iv; acc.y *= iv; acc.z *= iv; acc.w *= iv;
    acc.x = rna_tf32(acc.x > 0.f ? acc.x : expm1f(acc.x));
    acc.y = rna_tf32(acc.y > 0.f ? acc.y : expm1f(acc.y));
    acc.z = rna_tf32(acc.z > 0.f ? acc.z : expm1f(acc.z));
    acc.w = rna_tf32(acc.w > 0.f ? acc.w : expm1f(acc.w));
    ((float4*)out)[(size_t)d * 128 + t] = acc;
}

// ---------------- aggregation layer 2 -------------------------------------------
__global__ __launch_bounds__(64) void aggregate_l2_kernel(const float* __restrict__ Wh,
                                                          const float* __restrict__ val,
                                                          const float* __restrict__ inv,
                                                          float* __restrict__ out) {
    int d = blockIdx.x;
    int f = threadIdx.x;
    int beg = g_offsets[d], end = g_offsets[d + 1];
    float acc = 0.f;
    for (int p = beg; p < end; p++) {
        int src = g_csr_src[p];
        float ex = __ldg(&val[p]);
        if (f < OUTF) acc += ex * Wh[(size_t)src * 64 + f];
    }
    if (f < OUTF) out[(size_t)d * OUTF + f] = acc * __ldg(&inv[d]);
}

// ---------------- final elu + log_softmax ---------------------------------------
__global__ void final_kernel(const float* __restrict__ raw, float* __restrict__ out) {
    int w = (blockIdx.x * blockDim.x + threadIdx.x) >> 5;
    int lane = threadIdx.x & 31;
    if (w >= NN) return;
    int j0 = lane, j1 = lane + 32;
    float v0 = -1e30f, v1 = -1e30f;
    if (j0 < OUTF) {
        float x = raw[(size_t)w * OUTF + j0];
        v0 = x > 0.f ? x : expm1f(x);
    }
    if (j1 < OUTF) {
        float x = raw[(size_t)w * OUTF + j1];
        v1 = x > 0.f ? x : expm1f(x);
    }
    float m = fmaxf(v0, v1);
#pragma unroll
    for (int o = 16; o; o >>= 1) m = fmaxf(m, __shfl_xor_sync(0xffffffffu, m, o));
    float s = 0.f;
    if (j0 < OUTF) s += __expf(v0 - m);
    if (j1 < OUTF) s += __expf(v1 - m);
#pragma unroll
    for (int o = 16; o; o >>= 1) s += __shfl_xor_sync(0xffffffffu, s, o);
    float l = logf(s) + m;
    if (j0 < OUTF) out[(size_t)w * OUTF + j0] = v0 - l;
    if (j1 < OUTF) out[(size_t)w * OUTF + j1] = v1 - l;
}

// ---------------- host orchestration ---------------------------------------------
extern "C" void kernel_launch(void* const* d_in, const int* in_sizes, int n_in,
                              void* d_out, int out_size) {
    const float* x    = (const float*)d_in[0];
    const int*   ei   = (const int*)d_in[1];
    const float* W0   = (const float*)d_in[2];
    const float* a0   = (const float*)d_in[3];
    const float* W1   = (const float*)d_in[4];
    const float* a1   = (const float*)d_in[5];
    const float* Wout = (const float*)d_in[6];
    const float* aout = (const float*)d_in[7];
    float* out = (float*)d_out;

    float *Wc, *xr, *Wh, *h1, *h2, *ssrc, *sdst, *val, *inv;
    cudaGetSymbolAddress((void**)&Wc, g_Wc);
    cudaGetSymbolAddress((void**)&xr, g_xr);
    cudaGetSymbolAddress((void**)&Wh, g_Wh);
    cudaGetSymbolAddress((void**)&h1, g_h1);
    cudaGetSymbolAddress((void**)&h2, g_h2);
    cudaGetSymbolAddress((void**)&ssrc, g_ssrc);
    cudaGetSymbolAddress((void**)&sdst, g_sdst);
    cudaGetSymbolAddress((void**)&val, g_val);
    cudaGetSymbolAddress((void**)&inv, g_inv);

    static int smem_set = 0;
    if (!smem_set) {
        cudaFuncSetAttribute(gemm_tf32_kernel,
                             cudaFuncAttributeMaxDynamicSharedMemorySize, GEMM_SMEM_BYTES);
        smem_set = 1;
    }

    const int TB = 256;
    dim3 tf32_grid(4, (NN + 127) / 128);
    dim3 tf32_grid_out(1, (NN + 127) / 128);

    // Launch #4 (ncu capture point) = layer-0 tf32 GEMM.
    pack_kernel<<<(256 * 512 + TB - 1) / TB, TB>>>(W0, Wc, INF_, HEADS, HID);     // 1
    round_kernel<<<(NN * INF_ / 4 + TB - 1) / TB, TB>>>(x, xr, NN * INF_ / 4);     // 2
    zero_kernel<<<(NN + TB - 1) / TB, TB>>>();                                     // 3
    gemm_tf32_kernel<<<tf32_grid, 256, GEMM_SMEM_BYTES>>>(xr, Wc, Wh, NN, 512, INF_); // 4
    hist_kernel<<<(EP + TB - 1) / TB, TB>>>(ei);                                   // 5
    scan_kernel<<<1, 1024>>>();                                                    // 6
    fill_kernel<<<(EP + TB - 1) / TB, TB>>>(ei);                                   // 7
    scores8_kernel<<<(NN * 32 + TB - 1) / TB, TB>>>(Wh, a0, ssrc, sdst);
    alpha8_kernel<<<(NN + 7) / 8, 256>>>(ssrc, sdst, val, inv);
    aggregate512_kernel<<<NN, 128>>>(Wh, val, inv, h1);

    // ---- layer 1 ----
    pack_kernel<<<(512 * 512 + TB - 1) / TB, TB>>>(W1, Wc, 512, HEADS, HID);
    gemm_tf32_kernel<<<tf32_grid, 256, GEMM_SMEM_BYTES>>>(h1, Wc, Wh, NN, 512, 512);
    scores8_kernel<<<(NN * 32 + TB - 1) / TB, TB>>>(Wh, a1, ssrc, sdst);
    alpha8_kernel<<<(NN + 7) / 8, 256>>>(ssrc, sdst, val, inv);
    aggregate512_kernel<<<NN, 128>>>(Wh, val, inv, h2);

    // ---- layer 2 ----
    pack_out_kernel<<<(512 * 64 + TB - 1) / TB, TB>>>(Wout, Wc);
    gemm_tf32_kernel<<<tf32_grid_out, 256, GEMM_SMEM_BYTES>>>(h2, Wc, Wh, NN, 64, 512);
    scores_l2_kernel<<<(NN + TB - 1) / TB, TB>>>(Wh, aout, ssrc, sdst);
    alpha1_kernel<<<(NN + 7) / 8, 256>>>(ssrc, sdst, val, inv);
    aggregate_l2_kernel<<<NN, 64>>>(Wh, val, inv, h1);

    // ---- elu + log_softmax ----
    final_kernel<<<(NN + 7) / 8, 256>>>(h1, out);
}

// round 10
// speedup vs baseline: 1.1545x; 1.0461x over previous
#include <cuda_runtime.h>
#include <cuda_bf16.h>
#include <math.h>
#include <stdint.h>

#define NN 50000
#define EE 800000
#define EP (EE + NN)   // 850000 edges incl. self loops
#define HEADS 8
#define HID 64
#define INF_ 256
#define OUTF 40
#define LRELU 0.2f

// ---------------- scratch ------------------------------------------------------
__device__ float g_Wc0[256 * 512];
__device__ float g_Wc1[512 * 512];
__device__ float g_WcO[512 * 64];
__device__ float g_xr[(size_t)NN * INF_];
__device__ float g_Wh[(size_t)NN * 512];
__device__ float g_h1[(size_t)NN * 512];
__device__ float g_h2[(size_t)NN * 512];
__device__ float g_ssrc[NN * HEADS];
__device__ float g_sdst[NN * HEADS];
__device__ float g_val[(size_t)EP * HEADS];   // [h*EP + p]
__device__ float g_inv[NN * HEADS];
__device__ int   g_counts[NN];
__device__ int   g_offsets[NN + 1];
__device__ int   g_cursor[NN];
__device__ int   g_csr_src[EP];

// ---------------- tf32 helper ---------------------------------------------------
__device__ __forceinline__ float rna_tf32(float x) {
    unsigned r;
    asm("cvt.rna.tf32.f32 %0, %1;" : "=r"(r) : "f"(x));
    return __uint_as_float(r);
}

// ---------------- K1: fused zero + packs + round --------------------------------
// block ranges: [0,512) packW0 | [512,1536) packW1 | [1536,1664) packWout
//               [1664,14164) round | [14164,14360) zero
__global__ void prep_kernel(const float* __restrict__ W0, const float* __restrict__ W1,
                            const float* __restrict__ Wout, const float* __restrict__ x) {
    int b = blockIdx.x, tid = threadIdx.x;
    if (b < 512) {                           // packW0: [H,256,64] -> [256,512]
        int idx = b * 256 + tid;
        int k = idx >> 9, c = idx & 511;
        int h = c >> 6, j = c & 63;
        g_Wc0[idx] = rna_tf32(W0[(size_t)h * 256 * 64 + (size_t)k * 64 + j]);
    } else if (b < 1536) {                   // packW1: [H,512,64] -> [512,512]
        int idx = (b - 512) * 256 + tid;
        int k = idx >> 9, c = idx & 511;
        int h = c >> 6, j = c & 63;
        g_Wc1[idx] = rna_tf32(W1[(size_t)h * 512 * 64 + (size_t)k * 64 + j]);
    } else if (b < 1664) {                   // packWout: [512,40] -> [512,64] padded
        int idx = (b - 1536) * 256 + tid;
        int k = idx >> 6, c = idx & 63;
        g_WcO[idx] = (c < OUTF) ? rna_tf32(Wout[k * OUTF + c]) : 0.f;
    } else if (b < 14164) {                  // round x (float4): 3.2M elems
        int i = (b - 1664) * 256 + tid;
        if (i < NN * INF_ / 4) {
            float4 v = __ldg((const float4*)x + i);
            v.x = rna_tf32(v.x); v.y = rna_tf32(v.y);
            v.z = rna_tf32(v.z); v.w = rna_tf32(v.w);
            ((float4*)g_xr)[i] = v;
        }
    } else {                                 // zero counts/cursor
        int i = (b - 14164) * 256 + tid;
        if (i < NN) { g_counts[i] = 0; g_cursor[i] = 0; }
    }
}

// ---------------- cp.async helpers ---------------------------------------------
__device__ __forceinline__ void cp16(uint32_t dst, const void* src, bool pred) {
    int sz = pred ? 16 : 0;
    asm volatile("cp.async.ca.shared.global [%0], [%1], 16, %2;\n"
                 :: "r"(dst), "l"(src), "r"(sz));
}
#define CP_COMMIT() asm volatile("cp.async.commit_group;\n" ::: "memory")
#define CP_WAIT0()  asm volatile("cp.async.wait_group 0;\n" ::: "memory")
#define CP_WAIT1()  asm volatile("cp.async.wait_group 1;\n" ::: "memory")

// ---------------- TF32 GEMM body (3-stage, literal stages) ----------------------
#define APAD 20
#define BPAD 136
#define ASZ (128 * APAD)
#define BSZ (16 * BPAD)
#define STAGE_WORDS (ASZ + BSZ)
#define GEMM_SMEM_BYTES (STAGE_WORDS * 3 * 4)

__device__ __forceinline__ void gemm_body(const float* __restrict__ A,
                                          const float* __restrict__ B,
                                          float* __restrict__ C,
                                          int M, int Nc, int K,
                                          int bxx, int byy, unsigned* sm) {
    int tid = threadIdx.x;
    int wid = tid >> 5, lane = tid & 31;
    int ly = lane >> 2, lx = lane & 3;
    int wm = wid >> 1, wn = wid & 1;
    int bm = byy * 128, bn = bxx * 128;

    uint32_t sbase = (uint32_t)__cvta_generic_to_shared(sm);

    float c[2][8][4];
#pragma unroll
    for (int i = 0; i < 2; i++)
#pragma unroll
        for (int j = 0; j < 8; j++)
#pragma unroll
            for (int q = 0; q < 4; q++) c[i][j][q] = 0.f;

    int arow0 = tid >> 2, aq0 = tid & 3;
    int arow1 = (tid + 256) >> 2, aq1 = (tid + 256) & 3;
    int brow0 = tid >> 5, bq0 = tid & 31;
    int brow1 = (tid + 256) >> 5, bq1 = (tid + 256) & 31;
    bool bp0 = (bn + bq0 * 4 + 3) < Nc;
    bool bp1 = (bn + bq1 * 4 + 3) < Nc;

#define ISSUE(S, k0) do { \
        cp16(sbase + ((S) * STAGE_WORDS + arow0 * APAD + aq0 * 4) * 4, \
             A + (size_t)(bm + arow0) * K + (k0) + aq0 * 4, (bm + arow0) < M); \
        cp16(sbase + ((S) * STAGE_WORDS + arow1 * APAD + aq1 * 4) * 4, \
             A + (size_t)(bm + arow1) * K + (k0) + aq1 * 4, (bm + arow1) < M); \
        cp16(sbase + ((S) * STAGE_WORDS + ASZ + brow0 * BPAD + bq0 * 4) * 4, \
             B + (size_t)((k0) + brow0) * Nc + bn + bq0 * 4, bp0); \
        cp16(sbase + ((S) * STAGE_WORDS + ASZ + brow1 * BPAD + bq1 * 4) * 4, \
             B + (size_t)((k0) + brow1) * Nc + bn + bq1 * 4, bp1); \
        CP_COMMIT(); \
    } while (0)

#define BODY(S, t) do { \
        if ((t) + 2 < ntiles) { CP_WAIT1(); } else { CP_WAIT0(); } \
        __syncthreads(); \
        if ((t) + 2 < ntiles) ISSUE(((S) + 2) % 3, ((t) + 2) * 16); \
        const unsigned* Asc = sm + (S) * STAGE_WORDS; \
        const unsigned* Bsc = Asc + ASZ; \
        _Pragma("unroll") \
        for (int kk = 0; kk < 16; kk += 8) { \
            unsigned af[2][4]; \
            _Pragma("unroll") \
            for (int mt = 0; mt < 2; mt++) { \
                int mrow = wm * 32 + mt * 16 + ly; \
                af[mt][0] = Asc[(mrow) * APAD + kk + lx]; \
                af[mt][1] = Asc[(mrow + 8) * APAD + kk + lx]; \
                af[mt][2] = Asc[(mrow) * APAD + kk + lx + 4]; \
                af[mt][3] = Asc[(mrow + 8) * APAD + kk + lx + 4]; \
            } \
            unsigned bf[8][2]; \
            _Pragma("unroll") \
            for (int nt = 0; nt < 8; nt++) { \
                int ncol = wn * 64 + nt * 8 + ly; \
                bf[nt][0] = Bsc[(kk + lx) * BPAD + ncol]; \
                bf[nt][1] = Bsc[(kk + lx + 4) * BPAD + ncol]; \
            } \
            _Pragma("unroll") \
            for (int mt = 0; mt < 2; mt++) \
                _Pragma("unroll") \
                for (int nt = 0; nt < 8; nt++) { \
                    asm volatile( \
                        "mma.sync.aligned.m16n8k8.row.col.f32.tf32.tf32.f32 " \
                        "{%0,%1,%2,%3}, {%4,%5,%6,%7}, {%8,%9}, {%0,%1,%2,%3};\n" \
                        : "+f"(c[mt][nt][0]), "+f"(c[mt][nt][1]), \
                          "+f"(c[mt][nt][2]), "+f"(c[mt][nt][3]) \
                        : "r"(af[mt][0]), "r"(af[mt][1]), "r"(af[mt][2]), "r"(af[mt][3]), \
                          "r"(bf[nt][0]), "r"(bf[nt][1])); \
                } \
        } \
    } while (0)

    int ntiles = K / 16;
    ISSUE(0, 0);
    ISSUE(1, 16);

    int nfull = ntiles - (ntiles % 3);
    for (int t = 0; t < nfull; t += 3) {
        BODY(0, t);
        BODY(1, t + 1);
        BODY(2, t + 2);
    }
    if (ntiles % 3 >= 1) BODY(0, nfull);
    if (ntiles % 3 == 2) BODY(1, nfull + 1);
#undef BODY
#undef ISSUE

    __syncthreads();
#pragma unroll
    for (int mt = 0; mt < 2; mt++) {
#pragma unroll
        for (int nt = 0; nt < 8; nt++) {
            int r0 = bm + wm * 32 + mt * 16 + ly;
            int col = bn + wn * 64 + nt * 8 + 2 * lx;
            if (col < Nc) {
                if (r0 < M)
                    *(float2*)(C + (size_t)r0 * Nc + col) = make_float2(c[mt][nt][0], c[mt][nt][1]);
                int r1 = r0 + 8;
                if (r1 < M)
                    *(float2*)(C + (size_t)r1 * Nc + col) = make_float2(c[mt][nt][2], c[mt][nt][3]);
            }
        }
    }
}

// ---------------- standalone GEMM (layers 1, 2) ---------------------------------
__global__ __launch_bounds__(256) void gemm_tf32_kernel(const float* __restrict__ A,
                                                        const float* __restrict__ B,
                                                        float* __restrict__ C,
                                                        int M, int Nc, int K) {
    extern __shared__ unsigned sm[];
    gemm_body(A, B, C, M, Nc, K, blockIdx.x, blockIdx.y, sm);
}

// ---------------- K2: fused hist + gemm0 ----------------------------------------
#define HIST_BLKS 3321
__global__ __launch_bounds__(256) void hist_gemm_kernel(const int* __restrict__ ei,
                                                        const float* __restrict__ A,
                                                        const float* __restrict__ B,
                                                        float* __restrict__ C) {
    extern __shared__ unsigned sm[];
    int b = blockIdx.x;
    if (b < HIST_BLKS) {
        int e = b * 256 + threadIdx.x;
        if (e < EP) {
            int dst = (e < EE) ? ei[EE + e] : (e - EE);
            atomicAdd(&g_counts[dst], 1);
        }
        return;
    }
    int g = b - HIST_BLKS;
    gemm_body(A, B, C, NN, 512, INF_, g & 3, g >> 2, sm);
}

// ---------------- fast single-block scan (warp shuffles) ------------------------
__global__ void scan_kernel() {
    __shared__ int ws[33];
    int tid = threadIdx.x;
    int w = tid >> 5, lane = tid & 31;
    int carry = 0;
    for (int base = 0; base < NN; base += 1024) {
        int i = base + tid;
        int x = (i < NN) ? g_counts[i] : 0;
        int inc = x;
#pragma unroll
        for (int o = 1; o < 32; o <<= 1) {
            int t = __shfl_up_sync(0xffffffffu, inc, o);
            if (lane >= o) inc += t;
        }
        if (lane == 31) ws[w] = inc;
        __syncthreads();
        if (w == 0) {
            int t = (lane < 32) ? ws[lane] : 0;
            int ti = t;
#pragma unroll
            for (int o = 1; o < 32; o <<= 1) {
                int u = __shfl_up_sync(0xffffffffu, ti, o);
                if (lane >= o) ti += u;
            }
            ws[lane] = ti - t;      // exclusive warp prefix
            if (lane == 31) ws[32] = ti;  // tile total
        }
        __syncthreads();
        int excl = inc - x + ws[w] + carry;
        if (i < NN) g_offsets[i] = excl;
        carry += ws[32];
        __syncthreads();
    }
    if (tid == 0) g_offsets[NN] = carry;
}

// ---------------- K4: fused fill + scores8 --------------------------------------
#define FILL_BLKS 3321
__global__ void fill_scores_kernel(const int* __restrict__ ei,
                                   const float* __restrict__ Wh,
                                   const float* __restrict__ a,
                                   float* __restrict__ ssrc, float* __restrict__ sdst) {
    int b = blockIdx.x;
    if (b < FILL_BLKS) {
        int e = b * 256 + threadIdx.x;
        if (e < EP) {
            int src = (e < EE) ? ei[e] : (e - EE);
            int dst = (e < EE) ? ei[EE + e] : (e - EE);
            int pos = g_offsets[dst] + atomicAdd(&g_cursor[dst], 1);
            g_csr_src[pos] = src;
        }
        return;
    }
    int n = (b - FILL_BLKS) * 8 + (threadIdx.x >> 5);
    int lane = threadIdx.x & 31;
    if (n >= NN) return;
    int h = lane >> 2, q = lane & 3;
    const float* wp = Wh + (size_t)n * 512 + h * 64;
    const float* av = a + h * 128;
    float ss = 0.f, sd = 0.f;
#pragma unroll
    for (int it = 0; it < 4; it++) {
        int f = q * 4 + it * 16;
        float4 x  = *(const float4*)(wp + f);
        float4 as = __ldg((const float4*)(av + f));
        float4 ad = __ldg((const float4*)(av + 64 + f));
        ss += x.x * as.x + x.y * as.y + x.z * as.z + x.w * as.w;
        sd += x.x * ad.x + x.y * ad.y + x.z * ad.z + x.w * ad.w;
    }
    ss += __shfl_xor_sync(0xffffffffu, ss, 1);
    ss += __shfl_xor_sync(0xffffffffu, ss, 2);
    sd += __shfl_xor_sync(0xffffffffu, sd, 1);
    sd += __shfl_xor_sync(0xffffffffu, sd, 2);
    if (q == 0) { ssrc[n * 8 + h] = ss; sdst[n * 8 + h] = sd; }
}

// ---------------- standalone scores8 (layer 1) ----------------------------------
__global__ void scores8_kernel(const float* __restrict__ Wh, const float* __restrict__ a,
                               float* __restrict__ ssrc, float* __restrict__ sdst) {
    int n = (blockIdx.x * blockDim.x + threadIdx.x) >> 5;
    int lane = threadIdx.x & 31;
    if (n >= NN) return;
    int h = lane >> 2, q = lane & 3;
    const float* wp = Wh + (size_t)n * 512 + h * 64;
    const float* av = a + h * 128;
    float ss = 0.f, sd = 0.f;
#pragma unroll
    for (int it = 0; it < 4; it++) {
        int f = q * 4 + it * 16;
        float4 x  = *(const float4*)(wp + f);
        float4 as = __ldg((const float4*)(av + f));
        float4 ad = __ldg((const float4*)(av + 64 + f));
        ss += x.x * as.x + x.y * as.y + x.z * as.z + x.w * as.w;
        sd += x.x * ad.x + x.y * ad.y + x.z * ad.z + x.w * ad.w;
    }
    ss += __shfl_xor_sync(0xffffffffu, ss, 1);
    ss += __shfl_xor_sync(0xffffffffu, ss, 2);
    sd += __shfl_xor_sync(0xffffffffu, sd, 1);
    sd += __shfl_xor_sync(0xffffffffu, sd, 2);
    if (q == 0) { ssrc[n * 8 + h] = ss; sdst[n * 8 + h] = sd; }
}

// ---------------- scores layer 2 -------------------------------------------------
__global__ void scores_l2_kernel(const float* __restrict__ Wh, const float* __restrict__ a,
                                 float* __restrict__ ssrc, float* __restrict__ sdst) {
    int n = blockIdx.x * blockDim.x + threadIdx.x;
    if (n >= NN) return;
    const float* wp = Wh + (size_t)n * 64;
    float ss = 0.f, sd = 0.f;
#pragma unroll
    for (int j = 0; j < OUTF; j++) {
        float x = wp[j];
        ss += x * __ldg(a + j);
        sd += x * __ldg(a + OUTF + j);
    }
    ssrc[n] = ss;
    sdst[n] = sd;
}

// ---------------- segment softmax, 8 heads (pass1: max only; pass2: exp+write) --
__global__ void alpha8_kernel(const float* __restrict__ ssrc, const float* __restrict__ sdst,
                              float* __restrict__ val, float* __restrict__ inv) {
    int w = (blockIdx.x * blockDim.x + threadIdx.x) >> 5;
    int lane = threadIdx.x & 31;
    if (w >= NN) return;
    int beg = g_offsets[w], end = g_offsets[w + 1];
    float4 d0 = __ldg((const float4*)(sdst + w * 8));
    float4 d1 = __ldg((const float4*)(sdst + w * 8 + 4));
    float sdh[8] = {d0.x, d0.y, d0.z, d0.w, d1.x, d1.y, d1.z, d1.w};
    float m[8];
#pragma unroll
    for (int h = 0; h < 8; h++) m[h] = -1e30f;

    for (int p = beg + lane; p < end; p += 32) {
        int src = g_csr_src[p];
        float4 s0 = __ldg((const float4*)(ssrc + src * 8));
        float4 s1 = __ldg((const float4*)(ssrc + src * 8 + 4));
        float sv[8] = {s0.x, s0.y, s0.z, s0.w, s1.x, s1.y, s1.z, s1.w};
#pragma unroll
        for (int h = 0; h < 8; h++) {
            float v = sv[h] + sdh[h];
            v = v > 0.f ? v : LRELU * v;
            m[h] = fmaxf(m[h], v);
        }
    }
#pragma unroll
    for (int h = 0; h < 8; h++)
#pragma unroll
        for (int o = 16; o; o >>= 1) m[h] = fmaxf(m[h], __shfl_xor_sync(0xffffffffu, m[h], o));

    float s[8];
#pragma unroll
    for (int h = 0; h < 8; h++) s[h] = 0.f;
    for (int p = beg + lane; p < end; p += 32) {
        int src = g_csr_src[p];
        float4 s0 = __ldg((const float4*)(ssrc + src * 8));
        float4 s1 = __ldg((const float4*)(ssrc + src * 8 + 4));
        float sv[8] = {s0.x, s0.y, s0.z, s0.w, s1.x, s1.y, s1.z, s1.w};
#pragma unroll
        for (int h = 0; h < 8; h++) {
            float v = sv[h] + sdh[h];
            v = v > 0.f ? v : LRELU * v;
            float ex = __expf(v - m[h]);
            val[(size_t)h * EP + p] = ex;
            s[h] += ex;
        }
    }
#pragma unroll
    for (int h = 0; h < 8; h++)
#pragma unroll
        for (int o = 16; o; o >>= 1) s[h] += __shfl_xor_sync(0xffffffffu, s[h], o);
    if (lane == 0) {
#pragma unroll
        for (int h = 0; h < 8; h++) inv[w * 8 + h] = 1.0f / s[h];
    }
}

// ---------------- segment softmax, 1 head (layer 2) -----------------------------
__global__ void alpha1_kernel(const float* __restrict__ ssrc, const float* __restrict__ sdst,
                              float* __restrict__ val, float* __restrict__ inv) {
    int w = (blockIdx.x * blockDim.x + threadIdx.x) >> 5;
    int lane = threadIdx.x & 31;
    if (w >= NN) return;
    int beg = g_offsets[w], end = g_offsets[w + 1];
    float sdh = __ldg(sdst + w);
    float m = -1e30f;
    for (int p = beg + lane; p < end; p += 32) {
        float v = __ldg(ssrc + g_csr_src[p]) + sdh;
        v = v > 0.f ? v : LRELU * v;
        m = fmaxf(m, v);
    }
#pragma unroll
    for (int o = 16; o; o >>= 1) m = fmaxf(m, __shfl_xor_sync(0xffffffffu, m, o));
    float s = 0.f;
    for (int p = beg + lane; p < end; p += 32) {
        float v = __ldg(ssrc + g_csr_src[p]) + sdh;
        v = v > 0.f ? v : LRELU * v;
        float ex = __expf(v - m);
        val[p] = ex;
        s += ex;
    }
#pragma unroll
    for (int o = 16; o; o >>= 1) s += __shfl_xor_sync(0xffffffffu, s, o);
    if (lane == 0) inv[w] = 1.0f / s;
}

// ---------------- aggregation, Ftot=512 (unroll-2, epilogue elu+round) ----------
__global__ __launch_bounds__(128) void aggregate512_kernel(const float* __restrict__ Wh,
                                                           const float* __restrict__ val,
                                                           const float* __restrict__ inv,
                                                           float* __restrict__ out) {
    int d = blockIdx.x;
    int t = threadIdx.x;
    int h = t >> 4;
    int beg = g_offsets[d], end = g_offsets[d + 1];
    const float4* W4 = (const float4*)Wh;
    const float* vh = val + (size_t)h * EP;
    float4 acc = make_float4(0.f, 0.f, 0.f, 0.f);
    int p = beg;
    for (; p + 1 < end; p += 2) {
        int s0 = g_csr_src[p], s1 = g_csr_src[p + 1];
        float e0 = __ldg(&vh[p]);
        float e1 = __ldg(&vh[p + 1]);
        float4 w0 = __ldg(&W4[(size_t)s0 * 128 + t]);
        float4 w1 = __ldg(&W4[(size_t)s1 * 128 + t]);
        acc.x += e0 * w0.x + e1 * w1.x;
        acc.y += e0 * w0.y + e1 * w1.y;
        acc.z += e0 * w0.z + e1 * w1.z;
        acc.w += e0 * w0.w + e1 * w1.w;
    }
    if (p < end) {
        int s0 = g_csr_src[p];
        float e0 = __ldg(&vh[p]);
        float4 w0 = __ldg(&W4[(size_t)s0 * 128 + t]);
        acc.x += e0 * w0.x; acc.y += e0 * w0.y;
        acc.z += e0 * w0.z; acc.w += e0 * w0.w;
    }
    float iv = __ldg(&inv[d * 8 + h]);
    acc.x *= iv; acc.y *= iv; acc.z *= iv; acc.w *= iv;
    acc.x = rna_tf32(acc.x > 0.f ? acc.x : expm1f(acc.x));
    acc.y = rna_tf32(acc.y > 0.f ? acc.y : expm1f(acc.y));
    acc.z = rna_tf32(acc.z > 0.f ? acc.z : expm1f(acc.z));
    acc.w = rna_tf32(acc.w > 0.f ? acc.w : expm1f(acc.w));
    ((float4*)out)[(size_t)d * 128 + t] = acc;
}

// ---------------- aggregation layer 2 --------------------------------------------
__global__ __launch_bounds__(64) void aggregate_l2_kernel(const float* __restrict__ Wh,
                                                          const float* __restrict__ val,
                                                          const float* __restrict__ inv,
                                                          float* __restrict__ out) {
    int d = blockIdx.x;
    int f = threadIdx.x;
    int beg = g_offsets[d], end = g_offsets[d + 1];
    float acc = 0.f;
    for (int p = beg; p < end; p++) {
        int src = g_csr_src[p];
        float ex = __ldg(&val[p]);
        if (f < OUTF) acc += ex * Wh[(size_t)src * 64 + f];
    }
    if (f < OUTF) out[(size_t)d * OUTF + f] = acc * __ldg(&inv[d]);
}

// ---------------- final elu + log_softmax ----------------------------------------
__global__ void final_kernel(const float* __restrict__ raw, float* __restrict__ out) {
    int w = (blockIdx.x * blockDim.x + threadIdx.x) >> 5;
    int lane = threadIdx.x & 31;
    if (w >= NN) return;
    int j0 = lane, j1 = lane + 32;
    float v0 = -1e30f, v1 = -1e30f;
    if (j0 < OUTF) {
        float x = raw[(size_t)w * OUTF + j0];
        v0 = x > 0.f ? x : expm1f(x);
    }
    if (j1 < OUTF) {
        float x = raw[(size_t)w * OUTF + j1];
        v1 = x > 0.f ? x : expm1f(x);
    }
    float m = fmaxf(v0, v1);
#pragma unroll
    for (int o = 16; o; o >>= 1) m = fmaxf(m, __shfl_xor_sync(0xffffffffu, m, o));
    float s = 0.f;
    if (j0 < OUTF) s += __expf(v0 - m);
    if (j1 < OUTF) s += __expf(v1 - m);
#pragma unroll
    for (int o = 16; o; o >>= 1) s += __shfl_xor_sync(0xffffffffu, s, o);
    float l = logf(s) + m;
    if (j0 < OUTF) out[(size_t)w * OUTF + j0] = v0 - l;
    if (j1 < OUTF) out[(size_t)w * OUTF + j1] = v1 - l;
}

// ---------------- host orchestration ---------------------------------------------
extern "C" void kernel_launch(void* const* d_in, const int* in_sizes, int n_in,
                              void* d_out, int out_size) {
    const float* x    = (const float*)d_in[0];
    const int*   ei   = (const int*)d_in[1];
    const float* W0   = (const float*)d_in[2];
    const float* a0   = (const float*)d_in[3];
    const float* W1   = (const float*)d_in[4];
    const float* a1   = (const float*)d_in[5];
    const float* Wout = (const float*)d_in[6];
    const float* aout = (const float*)d_in[7];
    float* out = (float*)d_out;

    float *Wc0, *Wc1, *WcO, *xr, *Wh, *h1, *h2, *ssrc, *sdst, *val, *inv;
    cudaGetSymbolAddress((void**)&Wc0, g_Wc0);
    cudaGetSymbolAddress((void**)&Wc1, g_Wc1);
    cudaGetSymbolAddress((void**)&WcO, g_WcO);
    cudaGetSymbolAddress((void**)&xr, g_xr);
    cudaGetSymbolAddress((void**)&Wh, g_Wh);
    cudaGetSymbolAddress((void**)&h1, g_h1);
    cudaGetSymbolAddress((void**)&h2, g_h2);
    cudaGetSymbolAddress((void**)&ssrc, g_ssrc);
    cudaGetSymbolAddress((void**)&sdst, g_sdst);
    cudaGetSymbolAddress((void**)&val, g_val);
    cudaGetSymbolAddress((void**)&inv, g_inv);

    static int smem_set = 0;
    if (!smem_set) {
        cudaFuncSetAttribute(gemm_tf32_kernel,
                             cudaFuncAttributeMaxDynamicSharedMemorySize, GEMM_SMEM_BYTES);
        cudaFuncSetAttribute(hist_gemm_kernel,
                             cudaFuncAttributeMaxDynamicSharedMemorySize, GEMM_SMEM_BYTES);
        smem_set = 1;
    }

    const int TB = 256;
    dim3 tf32_grid(4, (NN + 127) / 128);         // 1564 blocks
    dim3 tf32_grid_out(1, (NN + 127) / 128);

    // 1: prep (zero + all packs + round)
    prep_kernel<<<14360, TB>>>(W0, W1, Wout, x);
    // 2: hist || gemm layer-0
    hist_gemm_kernel<<<HIST_BLKS + 1564, TB, GEMM_SMEM_BYTES>>>(ei, xr, Wc0, Wh);
    // 3: scan (fast)
    scan_kernel<<<1, 1024>>>();
    // 4: fill || scores8 layer-0   <- ncu capture point
    fill_scores_kernel<<<FILL_BLKS + (NN + 7) / 8, TB>>>(ei, Wh, a0, ssrc, sdst);
    // 5-6: layer-0 edge phase
    alpha8_kernel<<<(NN + 7) / 8, 256>>>(ssrc, sdst, val, inv);
    aggregate512_kernel<<<NN, 128>>>(Wh, val, inv, h1);

    // ---- layer 1 ----
    gemm_tf32_kernel<<<tf32_grid, 256, GEMM_SMEM_BYTES>>>(h1, Wc1, Wh, NN, 512, 512);
    scores8_kernel<<<(NN * 32 + TB - 1) / TB, TB>>>(Wh, a1, ssrc, sdst);
    alpha8_kernel<<<(NN + 7) / 8, 256>>>(ssrc, sdst, val, inv);
    aggregate512_kernel<<<NN, 128>>>(Wh, val, inv, h2);

    // ---- layer 2 ----
    gemm_tf32_kernel<<<tf32_grid_out, 256, GEMM_SMEM_BYTES>>>(h2, WcO, Wh, NN, 64, 512);
    scores_l2_kernel<<<(NN + TB - 1) / TB, TB>>>(Wh, aout, ssrc, sdst);
    alpha1_kernel<<<(NN + 7) / 8, 256>>>(ssrc, sdst, val, inv);
    aggregate_l2_kernel<<<NN, 64>>>(Wh, val, inv, h1);

    // ---- elu + log_softmax ----
    final_kernel<<<(NN + 7) / 8, 256>>>(h1, out);
}

// round 11
// speedup vs baseline: 1.2044x; 1.0432x over previous
#include <cuda_runtime.h>
#include <cuda_bf16.h>
#include <math.h>
#include <stdint.h>

#define NN 50000
#define EE 800000
#define EP (EE + NN)   // 850000 edges incl. self loops
#define HEADS 8
#define HID 64
#define INF_ 256
#define OUTF 40
#define LRELU 0.2f

// ---------------- scratch ------------------------------------------------------
__device__ float g_Wc0[256 * 512];
__device__ float g_Wc1[512 * 512];
__device__ float g_WcO[512 * 64];
__device__ float g_xr[(size_t)NN * INF_];
__device__ float g_Wh[(size_t)NN * 512];
__device__ float g_h1[(size_t)NN * 512];
__device__ float g_h2[(size_t)NN * 512];
__device__ float g_ssrc[NN * HEADS];
__device__ float g_sdst[NN * HEADS];
__device__ float g_val[(size_t)EP * HEADS];   // [h*EP + p]
__device__ float g_inv[NN * HEADS];
__device__ int   g_counts[NN];
__device__ int   g_offsets[NN + 1];
__device__ int   g_cursor[NN];
__device__ int   g_csr_src[EP];

// ---------------- tf32 helper ---------------------------------------------------
__device__ __forceinline__ float rna_tf32(float x) {
    unsigned r;
    asm("cvt.rna.tf32.f32 %0, %1;" : "=r"(r) : "f"(x));
    return __uint_as_float(r);
}

// ---------------- K1: fused zero + packs + round --------------------------------
__global__ void prep_kernel(const float* __restrict__ W0, const float* __restrict__ W1,
                            const float* __restrict__ Wout, const float* __restrict__ x) {
    int b = blockIdx.x, tid = threadIdx.x;
    if (b < 512) {                           // packW0: [H,256,64] -> [256,512]
        int idx = b * 256 + tid;
        int k = idx >> 9, c = idx & 511;
        int h = c >> 6, j = c & 63;
        g_Wc0[idx] = rna_tf32(W0[(size_t)h * 256 * 64 + (size_t)k * 64 + j]);
    } else if (b < 1536) {                   // packW1
        int idx = (b - 512) * 256 + tid;
        int k = idx >> 9, c = idx & 511;
        int h = c >> 6, j = c & 63;
        g_Wc1[idx] = rna_tf32(W1[(size_t)h * 512 * 64 + (size_t)k * 64 + j]);
    } else if (b < 1664) {                   // packWout padded
        int idx = (b - 1536) * 256 + tid;
        int k = idx >> 6, c = idx & 63;
        g_WcO[idx] = (c < OUTF) ? rna_tf32(Wout[k * OUTF + c]) : 0.f;
    } else if (b < 14164) {                  // round x
        int i = (b - 1664) * 256 + tid;
        if (i < NN * INF_ / 4) {
            float4 v = __ldg((const float4*)x + i);
            v.x = rna_tf32(v.x); v.y = rna_tf32(v.y);
            v.z = rna_tf32(v.z); v.w = rna_tf32(v.w);
            ((float4*)g_xr)[i] = v;
        }
    } else {                                 // zero counts/cursor
        int i = (b - 14164) * 256 + tid;
        if (i < NN) { g_counts[i] = 0; g_cursor[i] = 0; }
    }
}

// ---------------- cp.async helpers ---------------------------------------------
__device__ __forceinline__ void cp16(uint32_t dst, const void* src, bool pred) {
    int sz = pred ? 16 : 0;
    asm volatile("cp.async.ca.shared.global [%0], [%1], 16, %2;\n"
                 :: "r"(dst), "l"(src), "r"(sz));
}
#define CP_COMMIT() asm volatile("cp.async.commit_group;\n" ::: "memory")
#define CP_WAIT0()  asm volatile("cp.async.wait_group 0;\n" ::: "memory")
#define CP_WAIT1()  asm volatile("cp.async.wait_group 1;\n" ::: "memory")

// ---------------- TF32 GEMM body (3-stage) + optional fused scores epilogue -----
#define APAD 20
#define BPAD 136
#define ASZ (128 * APAD)
#define BSZ (16 * BPAD)
#define STAGE_WORDS (ASZ + BSZ)
#define GEMM_SMEM_BYTES (STAGE_WORDS * 3 * 4)

__device__ __forceinline__ void gemm_body(const float* __restrict__ A,
                                          const float* __restrict__ B,
                                          float* __restrict__ C,
                                          int M, int Nc, int K,
                                          int bxx, int byy, unsigned* sm,
                                          const float* __restrict__ avec,   // [H][128] or null
                                          float* __restrict__ ssrc,
                                          float* __restrict__ sdst) {
    int tid = threadIdx.x;
    int wid = tid >> 5, lane = tid & 31;
    int ly = lane >> 2, lx = lane & 3;
    int wm = wid >> 1, wn = wid & 1;
    int bm = byy * 128, bn = bxx * 128;

    uint32_t sbase = (uint32_t)__cvta_generic_to_shared(sm);

    float c[2][8][4];
#pragma unroll
    for (int i = 0; i < 2; i++)
#pragma unroll
        for (int j = 0; j < 8; j++)
#pragma unroll
            for (int q = 0; q < 4; q++) c[i][j][q] = 0.f;

    int arow0 = tid >> 2, aq0 = tid & 3;
    int arow1 = (tid + 256) >> 2, aq1 = (tid + 256) & 3;
    int brow0 = tid >> 5, bq0 = tid & 31;
    int brow1 = (tid + 256) >> 5, bq1 = (tid + 256) & 31;
    bool bp0 = (bn + bq0 * 4 + 3) < Nc;
    bool bp1 = (bn + bq1 * 4 + 3) < Nc;

#define ISSUE(S, k0) do { \
        cp16(sbase + ((S) * STAGE_WORDS + arow0 * APAD + aq0 * 4) * 4, \
             A + (size_t)(bm + arow0) * K + (k0) + aq0 * 4, (bm + arow0) < M); \
        cp16(sbase + ((S) * STAGE_WORDS + arow1 * APAD + aq1 * 4) * 4, \
             A + (size_t)(bm + arow1) * K + (k0) + aq1 * 4, (bm + arow1) < M); \
        cp16(sbase + ((S) * STAGE_WORDS + ASZ + brow0 * BPAD + bq0 * 4) * 4, \
             B + (size_t)((k0) + brow0) * Nc + bn + bq0 * 4, bp0); \
        cp16(sbase + ((S) * STAGE_WORDS + ASZ + brow1 * BPAD + bq1 * 4) * 4, \
             B + (size_t)((k0) + brow1) * Nc + bn + bq1 * 4, bp1); \
        CP_COMMIT(); \
    } while (0)

#define BODY(S, t) do { \
        if ((t) + 2 < ntiles) { CP_WAIT1(); } else { CP_WAIT0(); } \
        __syncthreads(); \
        if ((t) + 2 < ntiles) ISSUE(((S) + 2) % 3, ((t) + 2) * 16); \
        const unsigned* Asc = sm + (S) * STAGE_WORDS; \
        const unsigned* Bsc = Asc + ASZ; \
        _Pragma("unroll") \
        for (int kk = 0; kk < 16; kk += 8) { \
            unsigned af[2][4]; \
            _Pragma("unroll") \
            for (int mt = 0; mt < 2; mt++) { \
                int mrow = wm * 32 + mt * 16 + ly; \
                af[mt][0] = Asc[(mrow) * APAD + kk + lx]; \
                af[mt][1] = Asc[(mrow + 8) * APAD + kk + lx]; \
                af[mt][2] = Asc[(mrow) * APAD + kk + lx + 4]; \
                af[mt][3] = Asc[(mrow + 8) * APAD + kk + lx + 4]; \
            } \
            unsigned bf[8][2]; \
            _Pragma("unroll") \
            for (int nt = 0; nt < 8; nt++) { \
                int ncol = wn * 64 + nt * 8 + ly; \
                bf[nt][0] = Bsc[(kk + lx) * BPAD + ncol]; \
                bf[nt][1] = Bsc[(kk + lx + 4) * BPAD + ncol]; \
            } \
            _Pragma("unroll") \
            for (int mt = 0; mt < 2; mt++) \
                _Pragma("unroll") \
                for (int nt = 0; nt < 8; nt++) { \
                    asm volatile( \
                        "mma.sync.aligned.m16n8k8.row.col.f32.tf32.tf32.f32 " \
                        "{%0,%1,%2,%3}, {%4,%5,%6,%7}, {%8,%9}, {%0,%1,%2,%3};\n" \
                        : "+f"(c[mt][nt][0]), "+f"(c[mt][nt][1]), \
                          "+f"(c[mt][nt][2]), "+f"(c[mt][nt][3]) \
                        : "r"(af[mt][0]), "r"(af[mt][1]), "r"(af[mt][2]), "r"(af[mt][3]), \
                          "r"(bf[nt][0]), "r"(bf[nt][1])); \
                } \
        } \
    } while (0)

    int ntiles = K / 16;
    ISSUE(0, 0);
    ISSUE(1, 16);

    int nfull = ntiles - (ntiles % 3);
    for (int t = 0; t < nfull; t += 3) {
        BODY(0, t);
        BODY(1, t + 1);
        BODY(2, t + 2);
    }
    if (ntiles % 3 >= 1) BODY(0, nfull);
    if (ntiles % 3 == 2) BODY(1, nfull + 1);
#undef BODY
#undef ISSUE

    __syncthreads();
#pragma unroll
    for (int mt = 0; mt < 2; mt++) {
#pragma unroll
        for (int nt = 0; nt < 8; nt++) {
            int r0 = bm + wm * 32 + mt * 16 + ly;
            int col = bn + wn * 64 + nt * 8 + 2 * lx;
            if (col < Nc) {
                if (r0 < M)
                    *(float2*)(C + (size_t)r0 * Nc + col) = make_float2(c[mt][nt][0], c[mt][nt][1]);
                int r1 = r0 + 8;
                if (r1 < M)
                    *(float2*)(C + (size_t)r1 * Nc + col) = make_float2(c[mt][nt][2], c[mt][nt][3]);
            }
        }
    }

    // ---- fused attention-score epilogue (8-head layers) ----
    // Block column bxx covers heads 2bxx (wn=0 cols) and 2bxx+1 (wn=1 cols).
    if (avec) {
        int head = 2 * bxx + wn;
        const float* aH = avec + head * 128;
        float accs[2][2], accd[2][2];
#pragma unroll
        for (int mt = 0; mt < 2; mt++) { accs[mt][0] = accs[mt][1] = accd[mt][0] = accd[mt][1] = 0.f; }
#pragma unroll
        for (int nt = 0; nt < 8; nt++) {
            int jc = nt * 8 + 2 * lx;
            float a0s = __ldg(aH + jc), a1s = __ldg(aH + jc + 1);
            float a0d = __ldg(aH + 64 + jc), a1d = __ldg(aH + 64 + jc + 1);
#pragma unroll
            for (int mt = 0; mt < 2; mt++) {
                accs[mt][0] += c[mt][nt][0] * a0s + c[mt][nt][1] * a1s;
                accd[mt][0] += c[mt][nt][0] * a0d + c[mt][nt][1] * a1d;
                accs[mt][1] += c[mt][nt][2] * a0s + c[mt][nt][3] * a1s;
                accd[mt][1] += c[mt][nt][2] * a0d + c[mt][nt][3] * a1d;
            }
        }
#pragma unroll
        for (int mt = 0; mt < 2; mt++)
#pragma unroll
            for (int hf = 0; hf < 2; hf++) {
                accs[mt][hf] += __shfl_xor_sync(0xffffffffu, accs[mt][hf], 1);
                accs[mt][hf] += __shfl_xor_sync(0xffffffffu, accs[mt][hf], 2);
                accd[mt][hf] += __shfl_xor_sync(0xffffffffu, accd[mt][hf], 1);
                accd[mt][hf] += __shfl_xor_sync(0xffffffffu, accd[mt][hf], 2);
            }
        if (lx == 0) {
#pragma unroll
            for (int mt = 0; mt < 2; mt++)
#pragma unroll
                for (int hf = 0; hf < 2; hf++) {
                    int row = bm + wm * 32 + mt * 16 + ly + hf * 8;
                    if (row < M) {
                        ssrc[row * 8 + head] = accs[mt][hf];
                        sdst[row * 8 + head] = accd[mt][hf];
                    }
                }
        }
    }
}

// ---------------- standalone GEMM -----------------------------------------------
__global__ __launch_bounds__(256) void gemm_tf32_kernel(const float* __restrict__ A,
                                                        const float* __restrict__ B,
                                                        float* __restrict__ C,
                                                        int M, int Nc, int K,
                                                        const float* __restrict__ avec,
                                                        float* __restrict__ ssrc,
                                                        float* __restrict__ sdst) {
    extern __shared__ unsigned sm[];
    gemm_body(A, B, C, M, Nc, K, blockIdx.x, blockIdx.y, sm, avec, ssrc, sdst);
}

// ---------------- K2: fused hist + gemm0 (+scores) ------------------------------
#define HIST_BLKS 3321
__global__ __launch_bounds__(256) void hist_gemm_kernel(const int* __restrict__ ei,
                                                        const float* __restrict__ A,
                                                        const float* __restrict__ B,
                                                        float* __restrict__ C,
                                                        const float* __restrict__ avec,
                                                        float* __restrict__ ssrc,
                                                        float* __restrict__ sdst) {
    extern __shared__ unsigned sm[];
    int b = blockIdx.x;
    if (b < HIST_BLKS) {
        int e = b * 256 + threadIdx.x;
        if (e < EP) {
            int dst = (e < EE) ? ei[EE + e] : (e - EE);
            atomicAdd(&g_counts[dst], 1);
        }
        return;
    }
    int g = b - HIST_BLKS;
    gemm_body(A, B, C, NN, 512, INF_, g & 3, g >> 2, sm, avec, ssrc, sdst);
}

// ---------------- fast single-block scan ----------------------------------------
__global__ void scan_kernel() {
    __shared__ int ws[33];
    int tid = threadIdx.x;
    int w = tid >> 5, lane = tid & 31;
    int carry = 0;
    for (int base = 0; base < NN; base += 1024) {
        int i = base + tid;
        int x = (i < NN) ? g_counts[i] : 0;
        int inc = x;
#pragma unroll
        for (int o = 1; o < 32; o <<= 1) {
            int t = __shfl_up_sync(0xffffffffu, inc, o);
            if (lane >= o) inc += t;
        }
        if (lane == 31) ws[w] = inc;
        __syncthreads();
        if (w == 0) {
            int t = (lane < 32) ? ws[lane] : 0;
            int ti = t;
#pragma unroll
            for (int o = 1; o < 32; o <<= 1) {
                int u = __shfl_up_sync(0xffffffffu, ti, o);
                if (lane >= o) ti += u;
            }
            ws[lane] = ti - t;
            if (lane == 31) ws[32] = ti;
        }
        __syncthreads();
        int excl = inc - x + ws[w] + carry;
        if (i < NN) g_offsets[i] = excl;
        carry += ws[32];
        __syncthreads();
    }
    if (tid == 0) g_offsets[NN] = carry;
}

// ---------------- fill ------------------------------------------------------------
__global__ void fill_kernel(const int* __restrict__ ei) {
    int e = blockIdx.x * blockDim.x + threadIdx.x;
    if (e >= EP) return;
    int src = (e < EE) ? ei[e] : (e - EE);
    int dst = (e < EE) ? ei[EE + e] : (e - EE);
    int pos = g_offsets[dst] + atomicAdd(&g_cursor[dst], 1);
    g_csr_src[pos] = src;
}

// ---------------- scores layer 2 (H=1, F=40) --------------------------------------
__global__ void scores_l2_kernel(const float* __restrict__ Wh, const float* __restrict__ a,
                                 float* __restrict__ ssrc, float* __restrict__ sdst) {
    int n = blockIdx.x * blockDim.x + threadIdx.x;
    if (n >= NN) return;
    const float* wp = Wh + (size_t)n * 64;
    float ss = 0.f, sd = 0.f;
#pragma unroll
    for (int j = 0; j < OUTF; j++) {
        float x = wp[j];
        ss += x * __ldg(a + j);
        sd += x * __ldg(a + OUTF + j);
    }
    ssrc[n] = ss;
    sdst[n] = sd;
}

// ---------------- segment softmax, 8 heads ----------------------------------------
__global__ void alpha8_kernel(const float* __restrict__ ssrc, const float* __restrict__ sdst,
                              float* __restrict__ val, float* __restrict__ inv) {
    int w = (blockIdx.x * blockDim.x + threadIdx.x) >> 5;
    int lane = threadIdx.x & 31;
    if (w >= NN) return;
    int beg = g_offsets[w], end = g_offsets[w + 1];
    float4 d0 = __ldg((const float4*)(sdst + w * 8));
    float4 d1 = __ldg((const float4*)(sdst + w * 8 + 4));
    float sdh[8] = {d0.x, d0.y, d0.z, d0.w, d1.x, d1.y, d1.z, d1.w};
    float m[8];
#pragma unroll
    for (int h = 0; h < 8; h++) m[h] = -1e30f;

    for (int p = beg + lane; p < end; p += 32) {
        int src = g_csr_src[p];
        float4 s0 = __ldg((const float4*)(ssrc + src * 8));
        float4 s1 = __ldg((const float4*)(ssrc + src * 8 + 4));
        float sv[8] = {s0.x, s0.y, s0.z, s0.w, s1.x, s1.y, s1.z, s1.w};
#pragma unroll
        for (int h = 0; h < 8; h++) {
            float v = sv[h] + sdh[h];
            v = v > 0.f ? v : LRELU * v;
            m[h] = fmaxf(m[h], v);
        }
    }
#pragma unroll
    for (int h = 0; h < 8; h++)
#pragma unroll
        for (int o = 16; o; o >>= 1) m[h] = fmaxf(m[h], __shfl_xor_sync(0xffffffffu, m[h], o));

    float s[8];
#pragma unroll
    for (int h = 0; h < 8; h++) s[h] = 0.f;
    for (int p = beg + lane; p < end; p += 32) {
        int src = g_csr_src[p];
        float4 s0 = __ldg((const float4*)(ssrc + src * 8));
        float4 s1 = __ldg((const float4*)(ssrc + src * 8 + 4));
        float sv[8] = {s0.x, s0.y, s0.z, s0.w, s1.x, s1.y, s1.z, s1.w};
#pragma unroll
        for (int h = 0; h < 8; h++) {
            float v = sv[h] + sdh[h];
            v = v > 0.f ? v : LRELU * v;
            float ex = __expf(v - m[h]);
            val[(size_t)h * EP + p] = ex;
            s[h] += ex;
        }
    }
#pragma unroll
    for (int h = 0; h < 8; h++)
#pragma unroll
        for (int o = 16; o; o >>= 1) s[h] += __shfl_xor_sync(0xffffffffu, s[h], o);
    if (lane == 0) {
#pragma unroll
        for (int h = 0; h < 8; h++) inv[w * 8 + h] = 1.0f / s[h];
    }
}

// ---------------- segment softmax, 1 head -----------------------------------------
__global__ void alpha1_kernel(const float* __restrict__ ssrc, const float* __restrict__ sdst,
                              float* __restrict__ val, float* __restrict__ inv) {
    int w = (blockIdx.x * blockDim.x + threadIdx.x) >> 5;
    int lane = threadIdx.x & 31;
    if (w >= NN) return;
    int beg = g_offsets[w], end = g_offsets[w + 1];
    float sdh = __ldg(sdst + w);
    float m = -1e30f;
    for (int p = beg + lane; p < end; p += 32) {
        float v = __ldg(ssrc + g_csr_src[p]) + sdh;
        v = v > 0.f ? v : LRELU * v;
        m = fmaxf(m, v);
    }
#pragma unroll
    for (int o = 16; o; o >>= 1) m = fmaxf(m, __shfl_xor_sync(0xffffffffu, m, o));
    float s = 0.f;
    for (int p = beg + lane; p < end; p += 32) {
        float v = __ldg(ssrc + g_csr_src[p]) + sdh;
        v = v > 0.f ? v : LRELU * v;
        float ex = __expf(v - m);
        val[p] = ex;
        s += ex;
    }
#pragma unroll
    for (int o = 16; o; o >>= 1) s += __shfl_xor_sync(0xffffffffu, s, o);
    if (lane == 0) inv[w] = 1.0f / s;
}

// ---------------- aggregation, Ftot=512 -------------------------------------------
__global__ __launch_bounds__(128) void aggregate512_kernel(const float* __restrict__ Wh,
                                                           const float* __restrict__ val,
                                                           const float* __restrict__ inv,
                                                           float* __restrict__ out) {
    int d = blockIdx.x;
    int t = threadIdx.x;
    int h = t >> 4;
    int beg = g_offsets[d], end = g_offsets[d + 1];
    const float4* W4 = (const float4*)Wh;
    const float* vh = val + (size_t)h * EP;
    float4 acc = make_float4(0.f, 0.f, 0.f, 0.f);
    int p = beg;
    for (; p + 1 < end; p += 2) {
        int s0 = g_csr_src[p], s1 = g_csr_src[p + 1];
        float e0 = __ldg(&vh[p]);
        float e1 = __ldg(&vh[p + 1]);
        float4 w0 = __ldg(&W4[(size_t)s0 * 128 + t]);
        float4 w1 = __ldg(&W4[(size_t)s1 * 128 + t]);
        acc.x += e0 * w0.x + e1 * w1.x;
        acc.y += e0 * w0.y + e1 * w1.y;
        acc.z += e0 * w0.z + e1 * w1.z;
        acc.w += e0 * w0.w + e1 * w1.w;
    }
    if (p < end) {
        int s0 = g_csr_src[p];
        float e0 = __ldg(&vh[p]);
        float4 w0 = __ldg(&W4[(size_t)s0 * 128 + t]);
        acc.x += e0 * w0.x; acc.y += e0 * w0.y;
        acc.z += e0 * w0.z; acc.w += e0 * w0.w;
    }
    float iv = __ldg(&inv[d * 8 + h]);
    acc.x *= iv; acc.y *= iv; acc.z *= iv; acc.w *= iv;
    acc.x = rna_tf32(acc.x > 0.f ? acc.x : expm1f(acc.x));
    acc.y = rna_tf32(acc.y > 0.f ? acc.y : expm1f(acc.y));
    acc.z = rna_tf32(acc.z > 0.f ? acc.z : expm1f(acc.z));
    acc.w = rna_tf32(acc.w > 0.f ? acc.w : expm1f(acc.w));
    ((float4*)out)[(size_t)d * 128 + t] = acc;
}

// ---------------- aggregation layer 2 + fused elu + log_softmax -------------------
__global__ __launch_bounds__(64) void aggregate_l2_final_kernel(const float* __restrict__ Wh,
                                                                const float* __restrict__ val,
                                                                const float* __restrict__ inv,
                                                                float* __restrict__ out) {
    __shared__ float wred[2][2];
    int d = blockIdx.x;
    int f = threadIdx.x;
    int wp_ = f >> 5, lane = f & 31;
    int beg = g_offsets[d], end = g_offsets[d + 1];
    float acc = 0.f;
    for (int p = beg; p < end; p++) {
        int src = g_csr_src[p];
        float ex = __ldg(&val[p]);
        if (f < OUTF) acc += ex * Wh[(size_t)src * 64 + f];
    }
    float v = -1e30f;
    if (f < OUTF) {
        float o = acc * __ldg(&inv[d]);
        v = o > 0.f ? o : expm1f(o);
    }
    // block-wide max
    float m = v;
#pragma unroll
    for (int o = 16; o; o >>= 1) m = fmaxf(m, __shfl_xor_sync(0xffffffffu, m, o));
    if (lane == 0) wred[0][wp_] = m;
    __syncthreads();
    m = fmaxf(wred[0][0], wred[0][1]);
    // block-wide sum
    float e = (f < OUTF) ? __expf(v - m) : 0.f;
    float s = e;
#pragma unroll
    for (int o = 16; o; o >>= 1) s += __shfl_xor_sync(0xffffffffu, s, o);
    if (lane == 0) wred[1][wp_] = s;
    __syncthreads();
    s = wred[1][0] + wred[1][1];
    float l = logf(s) + m;
    if (f < OUTF) out[(size_t)d * OUTF + f] = v - l;
}

// ---------------- host orchestration ----------------------------------------------
extern "C" void kernel_launch(void* const* d_in, const int* in_sizes, int n_in,
                              void* d_out, int out_size) {
    const float* x    = (const float*)d_in[0];
    const int*   ei   = (const int*)d_in[1];
    const float* W0   = (const float*)d_in[2];
    const float* a0   = (const float*)d_in[3];
    const float* W1   = (const float*)d_in[4];
    const float* a1   = (const float*)d_in[5];
    const float* Wout = (const float*)d_in[6];
    const float* aout = (const float*)d_in[7];
    float* out = (float*)d_out;

    float *Wc0, *Wc1, *WcO, *xr, *Wh, *h1, *h2, *ssrc, *sdst, *val, *inv;
    cudaGetSymbolAddress((void**)&Wc0, g_Wc0);
    cudaGetSymbolAddress((void**)&Wc1, g_Wc1);
    cudaGetSymbolAddress((void**)&WcO, g_WcO);
    cudaGetSymbolAddress((void**)&xr, g_xr);
    cudaGetSymbolAddress((void**)&Wh, g_Wh);
    cudaGetSymbolAddress((void**)&h1, g_h1);
    cudaGetSymbolAddress((void**)&h2, g_h2);
    cudaGetSymbolAddress((void**)&ssrc, g_ssrc);
    cudaGetSymbolAddress((void**)&sdst, g_sdst);
    cudaGetSymbolAddress((void**)&val, g_val);
    cudaGetSymbolAddress((void**)&inv, g_inv);

    static int smem_set = 0;
    if (!smem_set) {
        cudaFuncSetAttribute(gemm_tf32_kernel,
                             cudaFuncAttributeMaxDynamicSharedMemorySize, GEMM_SMEM_BYTES);
        cudaFuncSetAttribute(hist_gemm_kernel,
                             cudaFuncAttributeMaxDynamicSharedMemorySize, GEMM_SMEM_BYTES);
        smem_set = 1;
    }

    const int TB = 256;
    dim3 tf32_grid(4, (NN + 127) / 128);
    dim3 tf32_grid_out(1, (NN + 127) / 128);

    // 1: prep (zero + packs + round)
    prep_kernel<<<14360, TB>>>(W0, W1, Wout, x);
    // 2: hist || gemm0 (+scores l0)
    hist_gemm_kernel<<<HIST_BLKS + 1564, TB, GEMM_SMEM_BYTES>>>(ei, xr, Wc0, Wh, a0, ssrc, sdst);
    // 3: scan
    scan_kernel<<<1, 1024>>>();
    // 4: fill
    fill_kernel<<<(EP + TB - 1) / TB, TB>>>(ei);
    // 5-6: layer-0 edge phase
    alpha8_kernel<<<(NN + 7) / 8, 256>>>(ssrc, sdst, val, inv);
    aggregate512_kernel<<<NN, 128>>>(Wh, val, inv, h1);

    // ---- layer 1 (gemm fused with scores) ----
    gemm_tf32_kernel<<<tf32_grid, 256, GEMM_SMEM_BYTES>>>(h1, Wc1, Wh, NN, 512, 512, a1, ssrc, sdst);
    alpha8_kernel<<<(NN + 7) / 8, 256>>>(ssrc, sdst, val, inv);
    aggregate512_kernel<<<NN, 128>>>(Wh, val, inv, h2);

    // ---- layer 2 ----
    gemm_tf32_kernel<<<tf32_grid_out, 256, GEMM_SMEM_BYTES>>>(h2, WcO, Wh, NN, 64, 512,
                                                              (const float*)nullptr, nullptr, nullptr);
    scores_l2_kernel<<<(NN + TB - 1) / TB, TB>>>(Wh, aout, ssrc, sdst);
    alpha1_kernel<<<(NN + 7) / 8, 256>>>(ssrc, sdst, val, inv);
    aggregate_l2_final_kernel<<<NN, 64>>>(Wh, val, inv, out);
}

// round 12
// speedup vs baseline: 1.3181x; 1.0945x over previous
#include <cuda_runtime.h>
#include <cuda_bf16.h>
#include <cuda_fp16.h>
#include <math.h>
#include <stdint.h>

#define NN 50000
#define EE 800000
#define EP (EE + NN)   // 850000 edges incl. self loops
#define HEADS 8
#define HID 64
#define INF_ 256
#define OUTF 40
#define LRELU 0.2f

// ---------------- scratch ------------------------------------------------------
__device__ float  g_Wc0[256 * 512];
__device__ float  g_Wc1[512 * 512];
__device__ float  g_WcO[512 * 64];
__device__ float  g_xr[(size_t)NN * INF_];
__device__ __half g_Wh16[(size_t)NN * 512];   // fp16 Wh for layers 0/1
__device__ float  g_Wh[(size_t)NN * 64];      // fp32 Wh for layer 2 (Nc=64)
__device__ float  g_h1[(size_t)NN * 512];
__device__ float  g_h2[(size_t)NN * 512];
__device__ float  g_ssrc[NN * HEADS];
__device__ float  g_sdst[NN * HEADS];
__device__ float  g_val[(size_t)EP * HEADS];  // [h*EP + p]
__device__ float  g_inv[NN * HEADS];
__device__ int    g_counts[NN];
__device__ int    g_offsets[NN + 1];
__device__ int    g_cursor[NN];
__device__ int    g_csr_src[EP];

// ---------------- tf32 helper ---------------------------------------------------
__device__ __forceinline__ float rna_tf32(float x) {
    unsigned r;
    asm("cvt.rna.tf32.f32 %0, %1;" : "=r"(r) : "f"(x));
    return __uint_as_float(r);
}

// ---------------- K1: fused zero + packs + round --------------------------------
__global__ void prep_kernel(const float* __restrict__ W0, const float* __restrict__ W1,
                            const float* __restrict__ Wout, const float* __restrict__ x) {
    int b = blockIdx.x, tid = threadIdx.x;
    if (b < 512) {                           // packW0: [H,256,64] -> [256,512]
        int idx = b * 256 + tid;
        int k = idx >> 9, c = idx & 511;
        int h = c >> 6, j = c & 63;
        g_Wc0[idx] = rna_tf32(W0[(size_t)h * 256 * 64 + (size_t)k * 64 + j]);
    } else if (b < 1536) {                   // packW1
        int idx = (b - 512) * 256 + tid;
        int k = idx >> 9, c = idx & 511;
        int h = c >> 6, j = c & 63;
        g_Wc1[idx] = rna_tf32(W1[(size_t)h * 512 * 64 + (size_t)k * 64 + j]);
    } else if (b < 1664) {                   // packWout padded
        int idx = (b - 1536) * 256 + tid;
        int k = idx >> 6, c = idx & 63;
        g_WcO[idx] = (c < OUTF) ? rna_tf32(Wout[k * OUTF + c]) : 0.f;
    } else if (b < 14164) {                  // round x
        int i = (b - 1664) * 256 + tid;
        if (i < NN * INF_ / 4) {
            float4 v = __ldg((const float4*)x + i);
            v.x = rna_tf32(v.x); v.y = rna_tf32(v.y);
            v.z = rna_tf32(v.z); v.w = rna_tf32(v.w);
            ((float4*)g_xr)[i] = v;
        }
    } else {                                 // zero counts/cursor
        int i = (b - 14164) * 256 + tid;
        if (i < NN) { g_counts[i] = 0; g_cursor[i] = 0; }
    }
}

// ---------------- cp.async helpers ---------------------------------------------
__device__ __forceinline__ void cp16(uint32_t dst, const void* src, bool pred) {
    int sz = pred ? 16 : 0;
    asm volatile("cp.async.ca.shared.global [%0], [%1], 16, %2;\n"
                 :: "r"(dst), "l"(src), "r"(sz));
}
#define CP_COMMIT() asm volatile("cp.async.commit_group;\n" ::: "memory")
#define CP_WAIT0()  asm volatile("cp.async.wait_group 0;\n" ::: "memory")
#define CP_WAIT1()  asm volatile("cp.async.wait_group 1;\n" ::: "memory")

// ---------------- TF32 GEMM body (3-stage) + fused scores + fp16/fp32 output ----
#define APAD 20
#define BPAD 136
#define ASZ (128 * APAD)
#define BSZ (16 * BPAD)
#define STAGE_WORDS (ASZ + BSZ)
#define GEMM_SMEM_BYTES (STAGE_WORDS * 3 * 4)

__device__ __forceinline__ void gemm_body(const float* __restrict__ A,
                                          const float* __restrict__ B,
                                          float* __restrict__ C,        // fp32 out (or null)
                                          __half* __restrict__ C16,     // fp16 out (or null)
                                          int M, int Nc, int K,
                                          int bxx, int byy, unsigned* sm,
                                          const float* __restrict__ avec,
                                          float* __restrict__ ssrc,
                                          float* __restrict__ sdst) {
    int tid = threadIdx.x;
    int wid = tid >> 5, lane = tid & 31;
    int ly = lane >> 2, lx = lane & 3;
    int wm = wid >> 1, wn = wid & 1;
    int bm = byy * 128, bn = bxx * 128;

    uint32_t sbase = (uint32_t)__cvta_generic_to_shared(sm);

    float c[2][8][4];
#pragma unroll
    for (int i = 0; i < 2; i++)
#pragma unroll
        for (int j = 0; j < 8; j++)
#pragma unroll
            for (int q = 0; q < 4; q++) c[i][j][q] = 0.f;

    int arow0 = tid >> 2, aq0 = tid & 3;
    int arow1 = (tid + 256) >> 2, aq1 = (tid + 256) & 3;
    int brow0 = tid >> 5, bq0 = tid & 31;
    int brow1 = (tid + 256) >> 5, bq1 = (tid + 256) & 31;
    bool bp0 = (bn + bq0 * 4 + 3) < Nc;
    bool bp1 = (bn + bq1 * 4 + 3) < Nc;

#define ISSUE(S, k0) do { \
        cp16(sbase + ((S) * STAGE_WORDS + arow0 * APAD + aq0 * 4) * 4, \
             A + (size_t)(bm + arow0) * K + (k0) + aq0 * 4, (bm + arow0) < M); \
        cp16(sbase + ((S) * STAGE_WORDS + arow1 * APAD + aq1 * 4) * 4, \
             A + (size_t)(bm + arow1) * K + (k0) + aq1 * 4, (bm + arow1) < M); \
        cp16(sbase + ((S) * STAGE_WORDS + ASZ + brow0 * BPAD + bq0 * 4) * 4, \
             B + (size_t)((k0) + brow0) * Nc + bn + bq0 * 4, bp0); \
        cp16(sbase + ((S) * STAGE_WORDS + ASZ + brow1 * BPAD + bq1 * 4) * 4, \
             B + (size_t)((k0) + brow1) * Nc + bn + bq1 * 4, bp1); \
        CP_COMMIT(); \
    } while (0)

#define BODY(S, t) do { \
        if ((t) + 2 < ntiles) { CP_WAIT1(); } else { CP_WAIT0(); } \
        __syncthreads(); \
        if ((t) + 2 < ntiles) ISSUE(((S) + 2) % 3, ((t) + 2) * 16); \
        const unsigned* Asc = sm + (S) * STAGE_WORDS; \
        const unsigned* Bsc = Asc + ASZ; \
        _Pragma("unroll") \
        for (int kk = 0; kk < 16; kk += 8) { \
            unsigned af[2][4]; \
            _Pragma("unroll") \
            for (int mt = 0; mt < 2; mt++) { \
                int mrow = wm * 32 + mt * 16 + ly; \
                af[mt][0] = Asc[(mrow) * APAD + kk + lx]; \
                af[mt][1] = Asc[(mrow + 8) * APAD + kk + lx]; \
                af[mt][2] = Asc[(mrow) * APAD + kk + lx + 4]; \
                af[mt][3] = Asc[(mrow + 8) * APAD + kk + lx + 4]; \
            } \
            unsigned bf[8][2]; \
            _Pragma("unroll") \
            for (int nt = 0; nt < 8; nt++) { \
                int ncol = wn * 64 + nt * 8 + ly; \
                bf[nt][0] = Bsc[(kk + lx) * BPAD + ncol]; \
                bf[nt][1] = Bsc[(kk + lx + 4) * BPAD + ncol]; \
            } \
            _Pragma("unroll") \
            for (int mt = 0; mt < 2; mt++) \
                _Pragma("unroll") \
                for (int nt = 0; nt < 8; nt++) { \
                    asm volatile( \
                        "mma.sync.aligned.m16n8k8.row.col.f32.tf32.tf32.f32 " \
                        "{%0,%1,%2,%3}, {%4,%5,%6,%7}, {%8,%9}, {%0,%1,%2,%3};\n" \
                        : "+f"(c[mt][nt][0]), "+f"(c[mt][nt][1]), \
                          "+f"(c[mt][nt][2]), "+f"(c[mt][nt][3]) \
                        : "r"(af[mt][0]), "r"(af[mt][1]), "r"(af[mt][2]), "r"(af[mt][3]), \
                          "r"(bf[nt][0]), "r"(bf[nt][1])); \
                } \
        } \
    } while (0)

    int ntiles = K / 16;
    ISSUE(0, 0);
    ISSUE(1, 16);

    int nfull = ntiles - (ntiles % 3);
    for (int t = 0; t < nfull; t += 3) {
        BODY(0, t);
        BODY(1, t + 1);
        BODY(2, t + 2);
    }
    if (ntiles % 3 >= 1) BODY(0, nfull);
    if (ntiles % 3 == 2) BODY(1, nfull + 1);
#undef BODY
#undef ISSUE

    __syncthreads();
    if (C) {
#pragma unroll
        for (int mt = 0; mt < 2; mt++) {
#pragma unroll
            for (int nt = 0; nt < 8; nt++) {
                int r0 = bm + wm * 32 + mt * 16 + ly;
                int col = bn + wn * 64 + nt * 8 + 2 * lx;
                if (col < Nc) {
                    if (r0 < M)
                        *(float2*)(C + (size_t)r0 * Nc + col) = make_float2(c[mt][nt][0], c[mt][nt][1]);
                    int r1 = r0 + 8;
                    if (r1 < M)
                        *(float2*)(C + (size_t)r1 * Nc + col) = make_float2(c[mt][nt][2], c[mt][nt][3]);
                }
            }
        }
    }
    if (C16) {
#pragma unroll
        for (int mt = 0; mt < 2; mt++) {
#pragma unroll
            for (int nt = 0; nt < 8; nt++) {
                int r0 = bm + wm * 32 + mt * 16 + ly;
                int col = bn + wn * 64 + nt * 8 + 2 * lx;
                if (col < Nc) {
                    if (r0 < M)
                        *(__half2*)(C16 + (size_t)r0 * Nc + col) =
                            __floats2half2_rn(c[mt][nt][0], c[mt][nt][1]);
                    int r1 = r0 + 8;
                    if (r1 < M)
                        *(__half2*)(C16 + (size_t)r1 * Nc + col) =
                            __floats2half2_rn(c[mt][nt][2], c[mt][nt][3]);
                }
            }
        }
    }

    // ---- fused attention-score epilogue (8-head layers) ----
    if (avec) {
        int head = 2 * bxx + wn;
        const float* aH = avec + head * 128;
        float accs[2][2], accd[2][2];
#pragma unroll
        for (int mt = 0; mt < 2; mt++) { accs[mt][0] = accs[mt][1] = accd[mt][0] = accd[mt][1] = 0.f; }
#pragma unroll
        for (int nt = 0; nt < 8; nt++) {
            int jc = nt * 8 + 2 * lx;
            float a0s = __ldg(aH + jc), a1s = __ldg(aH + jc + 1);
            float a0d = __ldg(aH + 64 + jc), a1d = __ldg(aH + 64 + jc + 1);
#pragma unroll
            for (int mt = 0; mt < 2; mt++) {
                accs[mt][0] += c[mt][nt][0] * a0s + c[mt][nt][1] * a1s;
                accd[mt][0] += c[mt][nt][0] * a0d + c[mt][nt][1] * a1d;
                accs[mt][1] += c[mt][nt][2] * a0s + c[mt][nt][3] * a1s;
                accd[mt][1] += c[mt][nt][2] * a0d + c[mt][nt][3] * a1d;
            }
        }
#pragma unroll
        for (int mt = 0; mt < 2; mt++)
#pragma unroll
            for (int hf = 0; hf < 2; hf++) {
                accs[mt][hf] += __shfl_xor_sync(0xffffffffu, accs[mt][hf], 1);
                accs[mt][hf] += __shfl_xor_sync(0xffffffffu, accs[mt][hf], 2);
                accd[mt][hf] += __shfl_xor_sync(0xffffffffu, accd[mt][hf], 1);
                accd[mt][hf] += __shfl_xor_sync(0xffffffffu, accd[mt][hf], 2);
            }
        if (lx == 0) {
#pragma unroll
            for (int mt = 0; mt < 2; mt++)
#pragma unroll
                for (int hf = 0; hf < 2; hf++) {
                    int row = bm + wm * 32 + mt * 16 + ly + hf * 8;
                    if (row < M) {
                        ssrc[row * 8 + head] = accs[mt][hf];
                        sdst[row * 8 + head] = accd[mt][hf];
                    }
                }
        }
    }
}

// ---------------- standalone GEMM -----------------------------------------------
__global__ __launch_bounds__(256) void gemm_tf32_kernel(const float* __restrict__ A,
                                                        const float* __restrict__ B,
                                                        float* __restrict__ C,
                                                        __half* __restrict__ C16,
                                                        int M, int Nc, int K,
                                                        const float* __restrict__ avec,
                                                        float* __restrict__ ssrc,
                                                        float* __restrict__ sdst) {
    extern __shared__ unsigned sm[];
    gemm_body(A, B, C, C16, M, Nc, K, blockIdx.x, blockIdx.y, sm, avec, ssrc, sdst);
}

// ---------------- K2: fused hist + gemm0 (+scores, fp16 out) --------------------
#define HIST_BLKS 3321
__global__ __launch_bounds__(256) void hist_gemm_kernel(const int* __restrict__ ei,
                                                        const float* __restrict__ A,
                                                        const float* __restrict__ B,
                                                        __half* __restrict__ C16,
                                                        const float* __restrict__ avec,
                                                        float* __restrict__ ssrc,
                                                        float* __restrict__ sdst) {
    extern __shared__ unsigned sm[];
    int b = blockIdx.x;
    if (b < HIST_BLKS) {
        int e = b * 256 + threadIdx.x;
        if (e < EP) {
            int dst = (e < EE) ? ei[EE + e] : (e - EE);
            atomicAdd(&g_counts[dst], 1);
        }
        return;
    }
    int g = b - HIST_BLKS;
    gemm_body(A, B, (float*)nullptr, C16, NN, 512, INF_, g & 3, g >> 2, sm, avec, ssrc, sdst);
}

// ---------------- fast single-block scan ----------------------------------------
__global__ void scan_kernel() {
    __shared__ int ws[33];
    int tid = threadIdx.x;
    int w = tid >> 5, lane = tid & 31;
    int carry = 0;
    for (int base = 0; base < NN; base += 1024) {
        int i = base + tid;
        int x = (i < NN) ? g_counts[i] : 0;
        int inc = x;
#pragma unroll
        for (int o = 1; o < 32; o <<= 1) {
            int t = __shfl_up_sync(0xffffffffu, inc, o);
            if (lane >= o) inc += t;
        }
        if (lane == 31) ws[w] = inc;
        __syncthreads();
        if (w == 0) {
            int t = (lane < 32) ? ws[lane] : 0;
            int ti = t;
#pragma unroll
            for (int o = 1; o < 32; o <<= 1) {
                int u = __shfl_up_sync(0xffffffffu, ti, o);
                if (lane >= o) ti += u;
            }
            ws[lane] = ti - t;
            if (lane == 31) ws[32] = ti;
        }
        __syncthreads();
        int excl = inc - x + ws[w] + carry;
        if (i < NN) g_offsets[i] = excl;
        carry += ws[32];
        __syncthreads();
    }
    if (tid == 0) g_offsets[NN] = carry;
}

// ---------------- fill ------------------------------------------------------------
__global__ void fill_kernel(const int* __restrict__ ei) {
    int e = blockIdx.x * blockDim.x + threadIdx.x;
    if (e >= EP) return;
    int src = (e < EE) ? ei[e] : (e - EE);
    int dst = (e < EE) ? ei[EE + e] : (e - EE);
    int pos = g_offsets[dst] + atomicAdd(&g_cursor[dst], 1);
    g_csr_src[pos] = src;
}

// ---------------- scores layer 2 (H=1, F=40, fp32 Wh stride 64) -------------------
__global__ void scores_l2_kernel(const float* __restrict__ Wh, const float* __restrict__ a,
                                 float* __restrict__ ssrc, float* __restrict__ sdst) {
    int n = blockIdx.x * blockDim.x + threadIdx.x;
    if (n >= NN) return;
    const float* wp = Wh + (size_t)n * 64;
    float ss = 0.f, sd = 0.f;
#pragma unroll
    for (int j = 0; j < OUTF; j++) {
        float x = wp[j];
        ss += x * __ldg(a + j);
        sd += x * __ldg(a + OUTF + j);
    }
    ssrc[n] = ss;
    sdst[n] = sd;
}

// ---------------- segment softmax, 8 heads ----------------------------------------
__global__ void alpha8_kernel(const float* __restrict__ ssrc, const float* __restrict__ sdst,
                              float* __restrict__ val, float* __restrict__ inv) {
    int w = (blockIdx.x * blockDim.x + threadIdx.x) >> 5;
    int lane = threadIdx.x & 31;
    if (w >= NN) return;
    int beg = g_offsets[w], end = g_offsets[w + 1];
    float4 d0 = __ldg((const float4*)(sdst + w * 8));
    float4 d1 = __ldg((const float4*)(sdst + w * 8 + 4));
    float sdh[8] = {d0.x, d0.y, d0.z, d0.w, d1.x, d1.y, d1.z, d1.w};
    float m[8];
#pragma unroll
    for (int h = 0; h < 8; h++) m[h] = -1e30f;

    for (int p = beg + lane; p < end; p += 32) {
        int src = g_csr_src[p];
        float4 s0 = __ldg((const float4*)(ssrc + src * 8));
        float4 s1 = __ldg((const float4*)(ssrc + src * 8 + 4));
        float sv[8] = {s0.x, s0.y, s0.z, s0.w, s1.x, s1.y, s1.z, s1.w};
#pragma unroll
        for (int h = 0; h < 8; h++) {
            float v = sv[h] + sdh[h];
            v = v > 0.f ? v : LRELU * v;
            m[h] = fmaxf(m[h], v);
        }
    }
#pragma unroll
    for (int h = 0; h < 8; h++)
#pragma unroll
        for (int o = 16; o; o >>= 1) m[h] = fmaxf(m[h], __shfl_xor_sync(0xffffffffu, m[h], o));

    float s[8];
#pragma unroll
    for (int h = 0; h < 8; h++) s[h] = 0.f;
    for (int p = beg + lane; p < end; p += 32) {
        int src = g_csr_src[p];
        float4 s0 = __ldg((const float4*)(ssrc + src * 8));
        float4 s1 = __ldg((const float4*)(ssrc + src * 8 + 4));
        float sv[8] = {s0.x, s0.y, s0.z, s0.w, s1.x, s1.y, s1.z, s1.w};
#pragma unroll
        for (int h = 0; h < 8; h++) {
            float v = sv[h] + sdh[h];
            v = v > 0.f ? v : LRELU * v;
            float ex = __expf(v - m[h]);
            val[(size_t)h * EP + p] = ex;
            s[h] += ex;
        }
    }
#pragma unroll
    for (int h = 0; h < 8; h++)
#pragma unroll
        for (int o = 16; o; o >>= 1) s[h] += __shfl_xor_sync(0xffffffffu, s[h], o);
    if (lane == 0) {
#pragma unroll
        for (int h = 0; h < 8; h++) inv[w * 8 + h] = 1.0f / s[h];
    }
}

// ---------------- segment softmax, 1 head -----------------------------------------
__global__ void alpha1_kernel(const float* __restrict__ ssrc, const float* __restrict__ sdst,
                              float* __restrict__ val, float* __restrict__ inv) {
    int w = (blockIdx.x * blockDim.x + threadIdx.x) >> 5;
    int lane = threadIdx.x & 31;
    if (w >= NN) return;
    int beg = g_offsets[w], end = g_offsets[w + 1];
    float sdh = __ldg(sdst + w);
    float m = -1e30f;
    for (int p = beg + lane; p < end; p += 32) {
        float v = __ldg(ssrc + g_csr_src[p]) + sdh;
        v = v > 0.f ? v : LRELU * v;
        m = fmaxf(m, v);
    }
#pragma unroll
    for (int o = 16; o; o >>= 1) m = fmaxf(m, __shfl_xor_sync(0xffffffffu, m, o));
    float s = 0.f;
    for (int p = beg + lane; p < end; p += 32) {
        float v = __ldg(ssrc + g_csr_src[p]) + sdh;
        v = v > 0.f ? v : LRELU * v;
        float ex = __expf(v - m);
        val[p] = ex;
        s += ex;
    }
#pragma unroll
    for (int o = 16; o; o >>= 1) s += __shfl_xor_sync(0xffffffffu, s, o);
    if (lane == 0) inv[w] = 1.0f / s;
}

// ---------------- aggregation, Ftot=512, fp16 Wh gather ---------------------------
__global__ __launch_bounds__(128) void aggregate512_kernel(const __half* __restrict__ Wh16,
                                                           const float* __restrict__ val,
                                                           const float* __restrict__ inv,
                                                           float* __restrict__ out) {
    int d = blockIdx.x;
    int t = threadIdx.x;           // 0..127, 4 halves each (8B)
    int h = t >> 4;
    int beg = g_offsets[d], end = g_offsets[d + 1];
    const uint2* W2 = (const uint2*)Wh16;   // row = 128 uint2 = 1KB
    const float* vh = val + (size_t)h * EP;
    float4 acc = make_float4(0.f, 0.f, 0.f, 0.f);
    int p = beg;
    for (; p + 1 < end; p += 2) {
        int s0 = g_csr_src[p], s1 = g_csr_src[p + 1];
        float e0 = __ldg(&vh[p]);
        float e1 = __ldg(&vh[p + 1]);
        uint2 u0 = __ldg(&W2[(size_t)s0 * 128 + t]);
        uint2 u1 = __ldg(&W2[(size_t)s1 * 128 + t]);
        float2 a0 = __half22float2(*(__half2*)&u0.x);
        float2 b0 = __half22float2(*(__half2*)&u0.y);
        float2 a1 = __half22float2(*(__half2*)&u1.x);
        float2 b1 = __half22float2(*(__half2*)&u1.y);
        acc.x += e0 * a0.x + e1 * a1.x;
        acc.y += e0 * a0.y + e1 * a1.y;
        acc.z += e0 * b0.x + e1 * b1.x;
        acc.w += e0 * b0.y + e1 * b1.y;
    }
    if (p < end) {
        int s0 = g_csr_src[p];
        float e0 = __ldg(&vh[p]);
        uint2 u0 = __ldg(&W2[(size_t)s0 * 128 + t]);
        float2 a0 = __half22float2(*(__half2*)&u0.x);
        float2 b0 = __half22float2(*(__half2*)&u0.y);
        acc.x += e0 * a0.x; acc.y += e0 * a0.y;
        acc.z += e0 * b0.x; acc.w += e0 * b0.y;
    }
    float iv = __ldg(&inv[d * 8 + h]);
    acc.x *= iv; acc.y *= iv; acc.z *= iv; acc.w *= iv;
    acc.x = rna_tf32(acc.x > 0.f ? acc.x : expm1f(acc.x));
    acc.y = rna_tf32(acc.y > 0.f ? acc.y : expm1f(acc.y));
    acc.z = rna_tf32(acc.z > 0.f ? acc.z : expm1f(acc.z));
    acc.w = rna_tf32(acc.w > 0.f ? acc.w : expm1f(acc.w));
    ((float4*)out)[(size_t)d * 128 + t] = acc;
}

// ---------------- aggregation layer 2 + fused elu + log_softmax -------------------
__global__ __launch_bounds__(64) void aggregate_l2_final_kernel(const float* __restrict__ Wh,
                                                                const float* __restrict__ val,
                                                                const float* __restrict__ inv,
                                                                float* __restrict__ out) {
    __shared__ float wred[2][2];
    int d = blockIdx.x;
    int f = threadIdx.x;
    int wp_ = f >> 5, lane = f & 31;
    int beg = g_offsets[d], end = g_offsets[d + 1];
    float acc = 0.f;
    for (int p = beg; p < end; p++) {
        int src = g_csr_src[p];
        float ex = __ldg(&val[p]);
        if (f < OUTF) acc += ex * Wh[(size_t)src * 64 + f];
    }
    float v = -1e30f;
    if (f < OUTF) {
        float o = acc * __ldg(&inv[d]);
        v = o > 0.f ? o : expm1f(o);
    }
    float m = v;
#pragma unroll
    for (int o = 16; o; o >>= 1) m = fmaxf(m, __shfl_xor_sync(0xffffffffu, m, o));
    if (lane == 0) wred[0][wp_] = m;
    __syncthreads();
    m = fmaxf(wred[0][0], wred[0][1]);
    float e = (f < OUTF) ? __expf(v - m) : 0.f;
    float s = e;
#pragma unroll
    for (int o = 16; o; o >>= 1) s += __shfl_xor_sync(0xffffffffu, s, o);
    if (lane == 0) wred[1][wp_] = s;
    __syncthreads();
    s = wred[1][0] + wred[1][1];
    float l = logf(s) + m;
    if (f < OUTF) out[(size_t)d * OUTF + f] = v - l;
}

// ---------------- host orchestration ----------------------------------------------
extern "C" void kernel_launch(void* const* d_in, const int* in_sizes, int n_in,
                              void* d_out, int out_size) {
    const float* x    = (const float*)d_in[0];
    const int*   ei   = (const int*)d_in[1];
    const float* W0   = (const float*)d_in[2];
    const float* a0   = (const float*)d_in[3];
    const float* W1   = (const float*)d_in[4];
    const float* a1   = (const float*)d_in[5];
    const float* Wout = (const float*)d_in[6];
    const float* aout = (const float*)d_in[7];
    float* out = (float*)d_out;

    float *Wc0, *Wc1, *WcO, *xr, *Wh, *h1, *h2, *ssrc, *sdst, *val, *inv;
    __half* Wh16;
    cudaGetSymbolAddress((void**)&Wc0, g_Wc0);
    cudaGetSymbolAddress((void**)&Wc1, g_Wc1);
    cudaGetSymbolAddress((void**)&WcO, g_WcO);
    cudaGetSymbolAddress((void**)&xr, g_xr);
    cudaGetSymbolAddress((void**)&Wh16, g_Wh16);
    cudaGetSymbolAddress((void**)&Wh, g_Wh);
    cudaGetSymbolAddress((void**)&h1, g_h1);
    cudaGetSymbolAddress((void**)&h2, g_h2);
    cudaGetSymbolAddress((void**)&ssrc, g_ssrc);
    cudaGetSymbolAddress((void**)&sdst, g_sdst);
    cudaGetSymbolAddress((void**)&val, g_val);
    cudaGetSymbolAddress((void**)&inv, g_inv);

    static int smem_set = 0;
    if (!smem_set) {
        cudaFuncSetAttribute(gemm_tf32_kernel,
                             cudaFuncAttributeMaxDynamicSharedMemorySize, GEMM_SMEM_BYTES);
        cudaFuncSetAttribute(hist_gemm_kernel,
                             cudaFuncAttributeMaxDynamicSharedMemorySize, GEMM_SMEM_BYTES);
        smem_set = 1;
    }

    const int TB = 256;
    dim3 tf32_grid(4, (NN + 127) / 128);
    dim3 tf32_grid_out(1, (NN + 127) / 128);

    // 1: prep (zero + packs + round)
    prep_kernel<<<14360, TB>>>(W0, W1, Wout, x);
    // 2: hist || gemm0 (+scores l0, fp16 Wh out)
    hist_gemm_kernel<<<HIST_BLKS + 1564, TB, GEMM_SMEM_BYTES>>>(ei, xr, Wc0, Wh16, a0, ssrc, sdst);
    // 3: scan
    scan_kernel<<<1, 1024>>>();
    // 4: fill
    fill_kernel<<<(EP + TB - 1) / TB, TB>>>(ei);
    // 5-6: layer-0 edge phase
    alpha8_kernel<<<(NN + 7) / 8, 256>>>(ssrc, sdst, val, inv);
    aggregate512_kernel<<<NN, 128>>>(Wh16, val, inv, h1);

    // ---- layer 1 (gemm fused with scores, fp16 Wh out) ----
    gemm_tf32_kernel<<<tf32_grid, 256, GEMM_SMEM_BYTES>>>(h1, Wc1, (float*)nullptr, Wh16,
                                                          NN, 512, 512, a1, ssrc, sdst);
    alpha8_kernel<<<(NN + 7) / 8, 256>>>(ssrc, sdst, val, inv);
    aggregate512_kernel<<<NN, 128>>>(Wh16, val, inv, h2);

    // ---- layer 2 (fp32 Wh, Nc=64) ----
    gemm_tf32_kernel<<<tf32_grid_out, 256, GEMM_SMEM_BYTES>>>(h2, WcO, Wh, (__half*)nullptr,
                                                              NN, 64, 512,
                                                              (const float*)nullptr, nullptr, nullptr);
    scores_l2_kernel<<<(NN + TB - 1) / TB, TB>>>(Wh, aout, ssrc, sdst);
    alpha1_kernel<<<(NN + 7) / 8, 256>>>(ssrc, sdst, val, inv);
    aggregate_l2_final_kernel<<<NN, 64>>>(Wh, val, inv, out);
}

// round 13
// speedup vs baseline: 1.6569x; 1.2570x over previous
#include <cuda_runtime.h>
#include <cuda_bf16.h>
#include <cuda_fp16.h>
#include <math.h>
#include <stdint.h>

#define NN 50000
#define EE 800000
#define EP (EE + NN)   // 850000 edges incl. self loops
#define HEADS 8
#define HID 64
#define INF_ 256
#define OUTF 40
#define LRELU 0.2f

// ---------------- scratch ------------------------------------------------------
__device__ __half g_Wc0h[512 * 256];          // [n][k] n-major, layer0 weights
__device__ __half g_Wc1h[512 * 512];          // [n][k]
__device__ __half g_WcOh[64 * 512];           // [n][k] padded to 64 n
__device__ __half g_x16[(size_t)NN * INF_];   // fp16 x
__device__ __half g_Wh16[(size_t)NN * 512];   // fp16 Wh (layers 0/1)
__device__ float  g_Wh[(size_t)NN * 64];      // fp32 Wh (layer 2)
__device__ __half g_h1h[(size_t)NN * 512];    // fp16 layer outputs
__device__ __half g_h2h[(size_t)NN * 512];
__device__ float  g_ssrc[NN * HEADS];
__device__ float  g_sdst[NN * HEADS];
__device__ float  g_val[(size_t)EP * HEADS];  // [h*EP + p]
__device__ float  g_inv[NN * HEADS];
__device__ int    g_counts[NN];
__device__ int    g_offsets[NN + 1];
__device__ int    g_cursor[NN];
__device__ int    g_csr_src[EP];

// ---------------- K1: fused zero + packs + x-convert -----------------------------
// [0,512) packW0 | [512,1536) packW1 | [1536,1664) packWout | [1664,14164) x | rest zero
__global__ void prep_kernel(const float* __restrict__ W0, const float* __restrict__ W1,
                            const float* __restrict__ Wout, const float* __restrict__ x) {
    int b = blockIdx.x, tid = threadIdx.x;
    if (b < 512) {                           // W0 [H,256,64] -> [n=512][k=256]
        int idx = b * 256 + tid;             // 131072 total
        int n = idx >> 8, k = idx & 255;
        int h = n >> 6, j = n & 63;
        g_Wc0h[idx] = __float2half_rn(W0[(size_t)h * 256 * 64 + (size_t)k * 64 + j]);
    } else if (b < 1536) {                   // W1 [H,512,64] -> [n=512][k=512]
        int idx = (b - 512) * 256 + tid;     // 262144 total
        int n = idx >> 9, k = idx & 511;
        int h = n >> 6, j = n & 63;
        g_Wc1h[idx] = __float2half_rn(W1[(size_t)h * 512 * 64 + (size_t)k * 64 + j]);
    } else if (b < 1664) {                   // Wout [512,40] -> [n=64][k=512]
        int idx = (b - 1536) * 256 + tid;    // 32768 total
        int n = idx >> 9, k = idx & 511;
        g_WcOh[idx] = (n < OUTF) ? __float2half_rn(Wout[k * OUTF + n]) : __float2half_rn(0.f);
    } else if (b < 14164) {                  // x -> fp16 (4 per thread)
        int i = (b - 1664) * 256 + tid;
        if (i < NN * INF_ / 4) {
            float4 v = __ldg((const float4*)x + i);
            __half2 lo = __floats2half2_rn(v.x, v.y);
            __half2 hi = __floats2half2_rn(v.z, v.w);
            uint2 u;
            u.x = *(unsigned*)&lo; u.y = *(unsigned*)&hi;
            ((uint2*)g_x16)[i] = u;
        }
    } else {
        int i = (b - 14164) * 256 + tid;
        if (i < NN) { g_counts[i] = 0; g_cursor[i] = 0; }
    }
}

// ---------------- cp.async helpers ---------------------------------------------
__device__ __forceinline__ void cp16(uint32_t dst, const void* src, bool pred) {
    int sz = pred ? 16 : 0;
    asm volatile("cp.async.ca.shared.global [%0], [%1], 16, %2;\n"
                 :: "r"(dst), "l"(src), "r"(sz));
}
#define CP_COMMIT() asm volatile("cp.async.commit_group;\n" ::: "memory")
#define CP_WAIT0()  asm volatile("cp.async.wait_group 0;\n" ::: "memory")
#define CP_WAIT1()  asm volatile("cp.async.wait_group 1;\n" ::: "memory")

// ---------------- FP16 GEMM body: BM=128 BN=128 BK=32, 3-stage -------------------
// A [M][K] row-major fp16; B [Nc][K] n-major fp16 (both K contiguous).
// 8 warps (4m x 2n), warp tile 32x64, mma.m16n8k16 fp32 accum.
#define APH 40                                   // halves per tile row (pad 32->40)
#define A_BYTES (128 * APH * 2)                  // 10240
#define STAGE_BYTES (2 * A_BYTES)                // A + B = 20480
#define GEMM_SMEM_BYTES (STAGE_BYTES * 3)        // 61440

__device__ __forceinline__ void gemm_body_h(const __half* __restrict__ A,
                                            const __half* __restrict__ B,
                                            float* __restrict__ C,
                                            __half* __restrict__ C16,
                                            int M, int Nc, int K,
                                            int bxx, int byy, char* smc,
                                            const float* __restrict__ avec,
                                            float* __restrict__ ssrc,
                                            float* __restrict__ sdst) {
    int tid = threadIdx.x;
    int wid = tid >> 5, lane = tid & 31;
    int ly = lane >> 2, lx = lane & 3;
    int wm = wid >> 1, wn = wid & 1;
    int bm = byy * 128, bn = bxx * 128;

    uint32_t sbase = (uint32_t)__cvta_generic_to_shared(smc);

    float c[2][8][4];
#pragma unroll
    for (int i = 0; i < 2; i++)
#pragma unroll
        for (int j = 0; j < 8; j++)
#pragma unroll
            for (int q = 0; q < 4; q++) c[i][j][q] = 0.f;

    // loaders: 512 16B-chunks per operand; chunk = row*4 + q
    int r0 = tid >> 2, q0 = tid & 3;
    int r1 = (tid + 256) >> 2, q1 = (tid + 256) & 3;
    bool ap0 = (bm + r0) < M, ap1 = (bm + r1) < M;
    bool bpr0 = (bn + r0) < Nc, bpr1 = (bn + r1) < Nc;

#define ISSUE(S, k0) do { \
        cp16(sbase + (S) * STAGE_BYTES + r0 * 80 + q0 * 16, \
             A + (size_t)(bm + r0) * K + (k0) + q0 * 8, ap0); \
        cp16(sbase + (S) * STAGE_BYTES + r1 * 80 + q1 * 16, \
             A + (size_t)(bm + r1) * K + (k0) + q1 * 8, ap1); \
        cp16(sbase + (S) * STAGE_BYTES + A_BYTES + r0 * 80 + q0 * 16, \
             B + (size_t)(bn + r0) * K + (k0) + q0 * 8, bpr0); \
        cp16(sbase + (S) * STAGE_BYTES + A_BYTES + r1 * 80 + q1 * 16, \
             B + (size_t)(bn + r1) * K + (k0) + q1 * 8, bpr1); \
        CP_COMMIT(); \
    } while (0)

#define BODY(S, t) do { \
        if ((t) + 2 < ntiles) { CP_WAIT1(); } else { CP_WAIT0(); } \
        __syncthreads(); \
        if ((t) + 2 < ntiles) ISSUE(((S) + 2) % 3, ((t) + 2) * 32); \
        const __half* Asc = (const __half*)(smc + (S) * STAGE_BYTES); \
        const __half* Bsc = (const __half*)(smc + (S) * STAGE_BYTES + A_BYTES); \
        _Pragma("unroll") \
        for (int kk = 0; kk < 32; kk += 16) { \
            unsigned af[2][4]; \
            _Pragma("unroll") \
            for (int mt = 0; mt < 2; mt++) { \
                int mrow = wm * 32 + mt * 16 + ly; \
                af[mt][0] = *(const unsigned*)&Asc[(mrow) * APH + kk + 2 * lx]; \
                af[mt][1] = *(const unsigned*)&Asc[(mrow + 8) * APH + kk + 2 * lx]; \
                af[mt][2] = *(const unsigned*)&Asc[(mrow) * APH + kk + 8 + 2 * lx]; \
                af[mt][3] = *(const unsigned*)&Asc[(mrow + 8) * APH + kk + 8 + 2 * lx]; \
            } \
            unsigned bf[8][2]; \
            _Pragma("unroll") \
            for (int nt = 0; nt < 8; nt++) { \
                int ncol = wn * 64 + nt * 8 + ly; \
                bf[nt][0] = *(const unsigned*)&Bsc[(ncol) * APH + kk + 2 * lx]; \
                bf[nt][1] = *(const unsigned*)&Bsc[(ncol) * APH + kk + 8 + 2 * lx]; \
            } \
            _Pragma("unroll") \
            for (int mt = 0; mt < 2; mt++) \
                _Pragma("unroll") \
                for (int nt = 0; nt < 8; nt++) { \
                    asm volatile( \
                        "mma.sync.aligned.m16n8k16.row.col.f32.f16.f16.f32 " \
                        "{%0,%1,%2,%3}, {%4,%5,%6,%7}, {%8,%9}, {%0,%1,%2,%3};\n" \
                        : "+f"(c[mt][nt][0]), "+f"(c[mt][nt][1]), \
                          "+f"(c[mt][nt][2]), "+f"(c[mt][nt][3]) \
                        : "r"(af[mt][0]), "r"(af[mt][1]), "r"(af[mt][2]), "r"(af[mt][3]), \
                          "r"(bf[nt][0]), "r"(bf[nt][1])); \
                } \
        } \
    } while (0)

    int ntiles = K / 32;
    ISSUE(0, 0);
    ISSUE(1, 32);

    int nfull = ntiles - (ntiles % 3);
    for (int t = 0; t < nfull; t += 3) {
        BODY(0, t);
        BODY(1, t + 1);
        BODY(2, t + 2);
    }
    if (ntiles % 3 >= 1) BODY(0, nfull);
    if (ntiles % 3 == 2) BODY(1, nfull + 1);
#undef BODY
#undef ISSUE

    __syncthreads();
    if (C) {
#pragma unroll
        for (int mt = 0; mt < 2; mt++)
#pragma unroll
            for (int nt = 0; nt < 8; nt++) {
                int r0_ = bm + wm * 32 + mt * 16 + ly;
                int col = bn + wn * 64 + nt * 8 + 2 * lx;
                if (col < Nc) {
                    if (r0_ < M)
                        *(float2*)(C + (size_t)r0_ * Nc + col) = make_float2(c[mt][nt][0], c[mt][nt][1]);
                    int r1_ = r0_ + 8;
                    if (r1_ < M)
                        *(float2*)(C + (size_t)r1_ * Nc + col) = make_float2(c[mt][nt][2], c[mt][nt][3]);
                }
            }
    }
    if (C16) {
#pragma unroll
        for (int mt = 0; mt < 2; mt++)
#pragma unroll
            for (int nt = 0; nt < 8; nt++) {
                int r0_ = bm + wm * 32 + mt * 16 + ly;
                int col = bn + wn * 64 + nt * 8 + 2 * lx;
                if (col < Nc) {
                    if (r0_ < M)
                        *(__half2*)(C16 + (size_t)r0_ * Nc + col) =
                            __floats2half2_rn(c[mt][nt][0], c[mt][nt][1]);
                    int r1_ = r0_ + 8;
                    if (r1_ < M)
                        *(__half2*)(C16 + (size_t)r1_ * Nc + col) =
                            __floats2half2_rn(c[mt][nt][2], c[mt][nt][3]);
                }
            }
    }

    // ---- fused attention-score epilogue (8-head layers) ----
    if (avec) {
        int head = 2 * bxx + wn;
        const float* aH = avec + head * 128;
        float accs[2][2], accd[2][2];
#pragma unroll
        for (int mt = 0; mt < 2; mt++) { accs[mt][0] = accs[mt][1] = accd[mt][0] = accd[mt][1] = 0.f; }
#pragma unroll
        for (int nt = 0; nt < 8; nt++) {
            int jc = nt * 8 + 2 * lx;
            float a0s = __ldg(aH + jc), a1s = __ldg(aH + jc + 1);
            float a0d = __ldg(aH + 64 + jc), a1d = __ldg(aH + 64 + jc + 1);
#pragma unroll
            for (int mt = 0; mt < 2; mt++) {
                accs[mt][0] += c[mt][nt][0] * a0s + c[mt][nt][1] * a1s;
                accd[mt][0] += c[mt][nt][0] * a0d + c[mt][nt][1] * a1d;
                accs[mt][1] += c[mt][nt][2] * a0s + c[mt][nt][3] * a1s;
                accd[mt][1] += c[mt][nt][2] * a0d + c[mt][nt][3] * a1d;
            }
        }
#pragma unroll
        for (int mt = 0; mt < 2; mt++)
#pragma unroll
            for (int hf = 0; hf < 2; hf++) {
                accs[mt][hf] += __shfl_xor_sync(0xffffffffu, accs[mt][hf], 1);
                accs[mt][hf] += __shfl_xor_sync(0xffffffffu, accs[mt][hf], 2);
                accd[mt][hf] += __shfl_xor_sync(0xffffffffu, accd[mt][hf], 1);
                accd[mt][hf] += __shfl_xor_sync(0xffffffffu, accd[mt][hf], 2);
            }
        if (lx == 0) {
#pragma unroll
            for (int mt = 0; mt < 2; mt++)
#pragma unroll
                for (int hf = 0; hf < 2; hf++) {
                    int row = bm + wm * 32 + mt * 16 + ly + hf * 8;
                    if (row < M) {
                        ssrc[row * 8 + head] = accs[mt][hf];
                        sdst[row * 8 + head] = accd[mt][hf];
                    }
                }
        }
    }
}

// ---------------- standalone GEMM ------------------------------------------------
__global__ __launch_bounds__(256) void gemm_h_kernel(const __half* __restrict__ A,
                                                     const __half* __restrict__ B,
                                                     float* __restrict__ C,
                                                     __half* __restrict__ C16,
                                                     int M, int Nc, int K,
                                                     const float* __restrict__ avec,
                                                     float* __restrict__ ssrc,
                                                     float* __restrict__ sdst) {
    extern __shared__ char smc[];
    gemm_body_h(A, B, C, C16, M, Nc, K, blockIdx.x, blockIdx.y, smc, avec, ssrc, sdst);
}

// ---------------- fused hist + gemm0 ---------------------------------------------
#define HIST_BLKS 3321
__global__ __launch_bounds__(256) void hist_gemm_kernel(const int* __restrict__ ei,
                                                        const __half* __restrict__ A,
                                                        const __half* __restrict__ B,
                                                        __half* __restrict__ C16,
                                                        const float* __restrict__ avec,
                                                        float* __restrict__ ssrc,
                                                        float* __restrict__ sdst) {
    extern __shared__ char smc[];
    int b = blockIdx.x;
    if (b < HIST_BLKS) {
        int e = b * 256 + threadIdx.x;
        if (e < EP) {
            int dst = (e < EE) ? ei[EE + e] : (e - EE);
            atomicAdd(&g_counts[dst], 1);
        }
        return;
    }
    int g = b - HIST_BLKS;
    gemm_body_h(A, B, (float*)nullptr, C16, NN, 512, INF_, g & 3, g >> 2, smc, avec, ssrc, sdst);
}

// ---------------- fast single-block scan ------------------------------------------
__global__ void scan_kernel() {
    __shared__ int ws[33];
    int tid = threadIdx.x;
    int w = tid >> 5, lane = tid & 31;
    int carry = 0;
    for (int base = 0; base < NN; base += 1024) {
        int i = base + tid;
        int x = (i < NN) ? g_counts[i] : 0;
        int inc = x;
#pragma unroll
        for (int o = 1; o < 32; o <<= 1) {
            int t = __shfl_up_sync(0xffffffffu, inc, o);
            if (lane >= o) inc += t;
        }
        if (lane == 31) ws[w] = inc;
        __syncthreads();
        if (w == 0) {
            int t = (lane < 32) ? ws[lane] : 0;
            int ti = t;
#pragma unroll
            for (int o = 1; o < 32; o <<= 1) {
                int u = __shfl_up_sync(0xffffffffu, ti, o);
                if (lane >= o) ti += u;
            }
            ws[lane] = ti - t;
            if (lane == 31) ws[32] = ti;
        }
        __syncthreads();
        int excl = inc - x + ws[w] + carry;
        if (i < NN) g_offsets[i] = excl;
        carry += ws[32];
        __syncthreads();
    }
    if (tid == 0) g_offsets[NN] = carry;
}

// ---------------- fill -------------------------------------------------------------
__global__ void fill_kernel(const int* __restrict__ ei) {
    int e = blockIdx.x * blockDim.x + threadIdx.x;
    if (e >= EP) return;
    int src = (e < EE) ? ei[e] : (e - EE);
    int dst = (e < EE) ? ei[EE + e] : (e - EE);
    int pos = g_offsets[dst] + atomicAdd(&g_cursor[dst], 1);
    g_csr_src[pos] = src;
}

// ---------------- scores layer 2 (H=1, F=40, fp32 Wh stride 64) --------------------
__global__ void scores_l2_kernel(const float* __restrict__ Wh, const float* __restrict__ a,
                                 float* __restrict__ ssrc, float* __restrict__ sdst) {
    int n = blockIdx.x * blockDim.x + threadIdx.x;
    if (n >= NN) return;
    const float* wp = Wh + (size_t)n * 64;
    float ss = 0.f, sd = 0.f;
#pragma unroll
    for (int j = 0; j < OUTF; j++) {
        float x = wp[j];
        ss += x * __ldg(a + j);
        sd += x * __ldg(a + OUTF + j);
    }
    ssrc[n] = ss;
    sdst[n] = sd;
}

// ---------------- segment softmax, 8 heads -----------------------------------------
__global__ void alpha8_kernel(const float* __restrict__ ssrc, const float* __restrict__ sdst,
                              float* __restrict__ val, float* __restrict__ inv) {
    int w = (blockIdx.x * blockDim.x + threadIdx.x) >> 5;
    int lane = threadIdx.x & 31;
    if (w >= NN) return;
    int beg = g_offsets[w], end = g_offsets[w + 1];
    float4 d0 = __ldg((const float4*)(sdst + w * 8));
    float4 d1 = __ldg((const float4*)(sdst + w * 8 + 4));
    float sdh[8] = {d0.x, d0.y, d0.z, d0.w, d1.x, d1.y, d1.z, d1.w};
    float m[8];
#pragma unroll
    for (int h = 0; h < 8; h++) m[h] = -1e30f;

    for (int p = beg + lane; p < end; p += 32) {
        int src = g_csr_src[p];
        float4 s0 = __ldg((const float4*)(ssrc + src * 8));
        float4 s1 = __ldg((const float4*)(ssrc + src * 8 + 4));
        float sv[8] = {s0.x, s0.y, s0.z, s0.w, s1.x, s1.y, s1.z, s1.w};
#pragma unroll
        for (int h = 0; h < 8; h++) {
            float v = sv[h] + sdh[h];
            v = v > 0.f ? v : LRELU * v;
            m[h] = fmaxf(m[h], v);
        }
    }
#pragma unroll
    for (int h = 0; h < 8; h++)
#pragma unroll
        for (int o = 16; o; o >>= 1) m[h] = fmaxf(m[h], __shfl_xor_sync(0xffffffffu, m[h], o));

    float s[8];
#pragma unroll
    for (int h = 0; h < 8; h++) s[h] = 0.f;
    for (int p = beg + lane; p < end; p += 32) {
        int src = g_csr_src[p];
        float4 s0 = __ldg((const float4*)(ssrc + src * 8));
        float4 s1 = __ldg((const float4*)(ssrc + src * 8 + 4));
        float sv[8] = {s0.x, s0.y, s0.z, s0.w, s1.x, s1.y, s1.z, s1.w};
#pragma unroll
        for (int h = 0; h < 8; h++) {
            float v = sv[h] + sdh[h];
            v = v > 0.f ? v : LRELU * v;
            float ex = __expf(v - m[h]);
            val[(size_t)h * EP + p] = ex;
            s[h] += ex;
        }
    }
#pragma unroll
    for (int h = 0; h < 8; h++)
#pragma unroll
        for (int o = 16; o; o >>= 1) s[h] += __shfl_xor_sync(0xffffffffu, s[h], o);
    if (lane == 0) {
#pragma unroll
        for (int h = 0; h < 8; h++) inv[w * 8 + h] = 1.0f / s[h];
    }
}

// ---------------- segment softmax, 1 head ------------------------------------------
__global__ void alpha1_kernel(const float* __restrict__ ssrc, const float* __restrict__ sdst,
                              float* __restrict__ val, float* __restrict__ inv) {
    int w = (blockIdx.x * blockDim.x + threadIdx.x) >> 5;
    int lane = threadIdx.x & 31;
    if (w >= NN) return;
    int beg = g_offsets[w], end = g_offsets[w + 1];
    float sdh = __ldg(sdst + w);
    float m = -1e30f;
    for (int p = beg + lane; p < end; p += 32) {
        float v = __ldg(ssrc + g_csr_src[p]) + sdh;
        v = v > 0.f ? v : LRELU * v;
        m = fmaxf(m, v);
    }
#pragma unroll
    for (int o = 16; o; o >>= 1) m = fmaxf(m, __shfl_xor_sync(0xffffffffu, m, o));
    float s = 0.f;
    for (int p = beg + lane; p < end; p += 32) {
        float v = __ldg(ssrc + g_csr_src[p]) + sdh;
        v = v > 0.f ? v : LRELU * v;
        float ex = __expf(v - m);
        val[p] = ex;
        s += ex;
    }
#pragma unroll
    for (int o = 16; o; o >>= 1) s += __shfl_xor_sync(0xffffffffu, s, o);
    if (lane == 0) inv[w] = 1.0f / s;
}

// ---------------- aggregation, Ftot=512, fp16 in/out -------------------------------
__global__ __launch_bounds__(128) void aggregate512_kernel(const __half* __restrict__ Wh16,
                                                           const float* __restrict__ val,
                                                           const float* __restrict__ inv,
                                                           __half* __restrict__ out16) {
    int d = blockIdx.x;
    int t = threadIdx.x;           // 0..127, 4 halves each
    int h = t >> 4;
    int beg = g_offsets[d], end = g_offsets[d + 1];
    const uint2* W2 = (const uint2*)Wh16;
    const float* vh = val + (size_t)h * EP;
    float4 acc = make_float4(0.f, 0.f, 0.f, 0.f);
    int p = beg;
    for (; p + 1 < end; p += 2) {
        int s0 = g_csr_src[p], s1 = g_csr_src[p + 1];
        float e0 = __ldg(&vh[p]);
        float e1 = __ldg(&vh[p + 1]);
        uint2 u0 = __ldg(&W2[(size_t)s0 * 128 + t]);
        uint2 u1 = __ldg(&W2[(size_t)s1 * 128 + t]);
        float2 a0 = __half22float2(*(__half2*)&u0.x);
        float2 b0 = __half22float2(*(__half2*)&u0.y);
        float2 a1 = __half22float2(*(__half2*)&u1.x);
        float2 b1 = __half22float2(*(__half2*)&u1.y);
        acc.x += e0 * a0.x + e1 * a1.x;
        acc.y += e0 * a0.y + e1 * a1.y;
        acc.z += e0 * b0.x + e1 * b1.x;
        acc.w += e0 * b0.y + e1 * b1.y;
    }
    if (p < end) {
        int s0 = g_csr_src[p];
        float e0 = __ldg(&vh[p]);
        uint2 u0 = __ldg(&W2[(size_t)s0 * 128 + t]);
        float2 a0 = __half22float2(*(__half2*)&u0.x);
        float2 b0 = __half22float2(*(__half2*)&u0.y);
        acc.x += e0 * a0.x; acc.y += e0 * a0.y;
        acc.z += e0 * b0.x; acc.w += e0 * b0.y;
    }
    float iv = __ldg(&inv[d * 8 + h]);
    acc.x *= iv; acc.y *= iv; acc.z *= iv; acc.w *= iv;
    acc.x = acc.x > 0.f ? acc.x : expm1f(acc.x);
    acc.y = acc.y > 0.f ? acc.y : expm1f(acc.y);
    acc.z = acc.z > 0.f ? acc.z : expm1f(acc.z);
    acc.w = acc.w > 0.f ? acc.w : expm1f(acc.w);
    __half2 lo = __floats2half2_rn(acc.x, acc.y);
    __half2 hi = __floats2half2_rn(acc.z, acc.w);
    uint2 u;
    u.x = *(unsigned*)&lo; u.y = *(unsigned*)&hi;
    ((uint2*)out16)[(size_t)d * 128 + t] = u;
}

// ---------------- aggregation layer 2 + fused elu + log_softmax --------------------
__global__ __launch_bounds__(64) void aggregate_l2_final_kernel(const float* __restrict__ Wh,
                                                                const float* __restrict__ val,
                                                                const float* __restrict__ inv,
                                                                float* __restrict__ out) {
    __shared__ float wred[2][2];
    int d = blockIdx.x;
    int f = threadIdx.x;
    int wp_ = f >> 5, lane = f & 31;
    int beg = g_offsets[d], end = g_offsets[d + 1];
    float acc = 0.f;
    for (int p = beg; p < end; p++) {
        int src = g_csr_src[p];
        float ex = __ldg(&val[p]);
        if (f < OUTF) acc += ex * Wh[(size_t)src * 64 + f];
    }
    float v = -1e30f;
    if (f < OUTF) {
        float o = acc * __ldg(&inv[d]);
        v = o > 0.f ? o : expm1f(o);
    }
    float m = v;
#pragma unroll
    for (int o = 16; o; o >>= 1) m = fmaxf(m, __shfl_xor_sync(0xffffffffu, m, o));
    if (lane == 0) wred[0][wp_] = m;
    __syncthreads();
    m = fmaxf(wred[0][0], wred[0][1]);
    float e = (f < OUTF) ? __expf(v - m) : 0.f;
    float s = e;
#pragma unroll
    for (int o = 16; o; o >>= 1) s += __shfl_xor_sync(0xffffffffu, s, o);
    if (lane == 0) wred[1][wp_] = s;
    __syncthreads();
    s = wred[1][0] + wred[1][1];
    float l = logf(s) + m;
    if (f < OUTF) out[(size_t)d * OUTF + f] = v - l;
}

// ---------------- host orchestration -----------------------------------------------
extern "C" void kernel_launch(void* const* d_in, const int* in_sizes, int n_in,
                              void* d_out, int out_size) {
    const float* x    = (const float*)d_in[0];
    const int*   ei   = (const int*)d_in[1];
    const float* W0   = (const float*)d_in[2];
    const float* a0   = (const float*)d_in[3];
    const float* W1   = (const float*)d_in[4];
    const float* a1   = (const float*)d_in[5];
    const float* Wout = (const float*)d_in[6];
    const float* aout = (const float*)d_in[7];
    float* out = (float*)d_out;

    __half *Wc0h, *Wc1h, *WcOh, *x16, *Wh16, *h1h, *h2h;
    float *Wh, *ssrc, *sdst, *val, *inv;
    cudaGetSymbolAddress((void**)&Wc0h, g_Wc0h);
    cudaGetSymbolAddress((void**)&Wc1h, g_Wc1h);
    cudaGetSymbolAddress((void**)&WcOh, g_WcOh);
    cudaGetSymbolAddress((void**)&x16, g_x16);
    cudaGetSymbolAddress((void**)&Wh16, g_Wh16);
    cudaGetSymbolAddress((void**)&Wh, g_Wh);
    cudaGetSymbolAddress((void**)&h1h, g_h1h);
    cudaGetSymbolAddress((void**)&h2h, g_h2h);
    cudaGetSymbolAddress((void**)&ssrc, g_ssrc);
    cudaGetSymbolAddress((void**)&sdst, g_sdst);
    cudaGetSymbolAddress((void**)&val, g_val);
    cudaGetSymbolAddress((void**)&inv, g_inv);

    static int smem_set = 0;
    if (!smem_set) {
        cudaFuncSetAttribute(gemm_h_kernel,
                             cudaFuncAttributeMaxDynamicSharedMemorySize, GEMM_SMEM_BYTES);
        cudaFuncSetAttribute(hist_gemm_kernel,
                             cudaFuncAttributeMaxDynamicSharedMemorySize, GEMM_SMEM_BYTES);
        smem_set = 1;
    }

    const int TB = 256;
    dim3 gh_grid(4, (NN + 127) / 128);
    dim3 gh_grid_out(1, (NN + 127) / 128);

    // 1: prep
    prep_kernel<<<14360, TB>>>(W0, W1, Wout, x);
    // 2: hist || gemm0 (+scores l0)
    hist_gemm_kernel<<<HIST_BLKS + 1564, TB, GEMM_SMEM_BYTES>>>(ei, x16, Wc0h, Wh16, a0, ssrc, sdst);
    // 3: scan
    scan_kernel<<<1, 1024>>>();
    // 4: fill
    fill_kernel<<<(EP + TB - 1) / TB, TB>>>(ei);
    // 5-6: layer-0 edge phase
    alpha8_kernel<<<(NN + 7) / 8, 256>>>(ssrc, sdst, val, inv);
    aggregate512_kernel<<<NN, 128>>>(Wh16, val, inv, h1h);

    // ---- layer 1 ----
    gemm_h_kernel<<<gh_grid, 256, GEMM_SMEM_BYTES>>>(h1h, Wc1h, (float*)nullptr, Wh16,
                                                     NN, 512, 512, a1, ssrc, sdst);
    alpha8_kernel<<<(NN + 7) / 8, 256>>>(ssrc, sdst, val, inv);
    aggregate512_kernel<<<NN, 128>>>(Wh16, val, inv, h2h);

    // ---- layer 2 ----
    gemm_h_kernel<<<gh_grid_out, 256, GEMM_SMEM_BYTES>>>(h2h, WcOh, Wh, (__half*)nullptr,
                                                         NN, 64, 512,
                                                         (const float*)nullptr, nullptr, nullptr);
    scores_l2_kernel<<<(NN + TB - 1) / TB, TB>>>(Wh, aout, ssrc, sdst);
    alpha1_kernel<<<(NN + 7) / 8, 256>>>(ssrc, sdst, val, inv);
    aggregate_l2_final_kernel<<<NN, 64>>>(Wh, val, inv, out);
}